// round 5
// baseline (speedup 1.0000x reference)
#include <cuda_runtime.h>
#include <math.h>

#define T_LEN 100000
#define WIN   336
#define OUTSZ 48
#define SEAS  168
#define N_ROWS (T_LEN - WIN - OUTSZ + 1)   // 99617
#define STD_NOISE 0.001f
#define LVP_F 50.0f
#define CHUNK 160                           // must be <= SEAS
#define LPL 5                               // elements per lane (CHUNK/32)

// ---------------- device scratch (static globals: no allocation) ----------------
__device__ float g_levels[T_LEN];
__device__ float g_wall[T_LEN];
__device__ float g_llev[T_LEN];     // log(levels[i])
__device__ float g_c[T_LEN];        // log(x[i]) - log(w_all[i])
__device__ float g_inputs[(size_t)N_ROWS * WIN];   // ~128 MiB
__device__ float g_hidden[(size_t)N_ROWS * WIN];   // ~128 MiB

// ---------------- compile-time threefry for key derivation ----------------
struct TF2 { unsigned y0, y1; };
__host__ __device__ constexpr unsigned tf_rotl(unsigned x, int r) {
    return (x << r) | (x >> (32 - r));
}
__host__ __device__ constexpr TF2 tf2x32_const(unsigned k0, unsigned k1,
                                               unsigned x0, unsigned x1) {
    unsigned ks2 = 0x1BD11BDAu ^ k0 ^ k1;
    const int R[8] = {13, 15, 26, 6, 17, 29, 16, 24};
    x0 += k0; x1 += k1;
    for (int i = 0; i < 4; i++) { x0 += x1; x1 = tf_rotl(x1, R[i]); x1 ^= x0; }
    x0 += k1;  x1 += ks2 + 1u;
    for (int i = 4; i < 8; i++) { x0 += x1; x1 = tf_rotl(x1, R[i]); x1 ^= x0; }
    x0 += ks2; x1 += k0 + 2u;
    for (int i = 0; i < 4; i++) { x0 += x1; x1 = tf_rotl(x1, R[i]); x1 ^= x0; }
    x0 += k0;  x1 += k1 + 3u;
    for (int i = 4; i < 8; i++) { x0 += x1; x1 = tf_rotl(x1, R[i]); x1 ^= x0; }
    x0 += k1;  x1 += ks2 + 4u;
    for (int i = 0; i < 4; i++) { x0 += x1; x1 = tf_rotl(x1, R[i]); x1 ^= x0; }
    x0 += ks2; x1 += k0 + 5u;
    return TF2{x0, x1};
}
// PARTITIONABLE threefry (modern JAX default):
//   split(key(1)):  key_i = threefry((0,1), (0, i))  -> full (y0,y1) is the new key
//   random_bits(key, 32, shape): element i uses counter (0, i), harvests y0 ^ y1

// ---------------- runtime threefry2x32 (JAX-exact) ----------------
__device__ __forceinline__ void threefry2x32(unsigned k0, unsigned k1,
                                             unsigned x0, unsigned x1,
                                             unsigned& y0, unsigned& y1) {
    unsigned ks2 = 0x1BD11BDAu ^ k0 ^ k1;
#define TF_RND(r) { x0 += x1; x1 = (x1 << (r)) | (x1 >> (32 - (r))); x1 ^= x0; }
    x0 += k0; x1 += k1;
    TF_RND(13) TF_RND(15) TF_RND(26) TF_RND(6)
    x0 += k1;  x1 += ks2 + 1u;
    TF_RND(17) TF_RND(29) TF_RND(16) TF_RND(24)
    x0 += ks2; x1 += k0 + 2u;
    TF_RND(13) TF_RND(15) TF_RND(26) TF_RND(6)
    x0 += k0;  x1 += k1 + 3u;
    TF_RND(17) TF_RND(29) TF_RND(16) TF_RND(24)
    x0 += k1;  x1 += ks2 + 4u;
    TF_RND(13) TF_RND(15) TF_RND(26) TF_RND(6)
    x0 += ks2; x1 += k0 + 5u;
#undef TF_RND
    y0 = x0; y1 = x1;
}

// partitionable 32-bit draw for flat index i (i < 2^32): counter (0, i), bits = y0^y1
__device__ __forceinline__ unsigned tf_bits32(unsigned k0, unsigned k1, unsigned i) {
    unsigned y0, y1;
    threefry2x32(k0, k1, 0u, i, y0, y1);
    return y0 ^ y1;
}

// bits -> N(0,1), matching jax.random.normal (uniform(nextafter(-1,0),1) -> sqrt2*erfinv)
__device__ __forceinline__ float bits_to_normal(unsigned bits) {
    float f = __uint_as_float((bits >> 9) | 0x3f800000u) - 1.0f;   // [0,1)
    const float LO = -0.99999994f;
    float u = fmaxf(LO, f * 2.0f + LO);    // (1 - LO) rounds to 2.0f in fp32
    float x = u;
    float w = -log1pf(-x * x);
    float p;
    if (w < 5.0f) {
        w -= 2.5f;
        p =              2.81022636e-08f;
        p = fmaf(p, w,   3.43273939e-07f);
        p = fmaf(p, w,  -3.5233877e-06f);
        p = fmaf(p, w,  -4.39150654e-06f);
        p = fmaf(p, w,   0.00021858087f);
        p = fmaf(p, w,  -0.00125372503f);
        p = fmaf(p, w,  -0.00417768164f);
        p = fmaf(p, w,   0.246640727f);
        p = fmaf(p, w,   1.50140941f);
    } else {
        w = sqrtf(w) - 3.0f;
        p =             -0.000200214257f;
        p = fmaf(p, w,   0.000100950558f);
        p = fmaf(p, w,   0.00134934322f);
        p = fmaf(p, w,  -0.00367342844f);
        p = fmaf(p, w,   0.00573950773f);
        p = fmaf(p, w,  -0.0076224613f);
        p = fmaf(p, w,   0.00943887047f);
        p = fmaf(p, w,   1.00167406f);
        p = fmaf(p, w,   2.83297682f);
    }
    return 1.41421356237f * (p * x);
}

// ---------------- warp-parallel chunked ES scan ----------------
__global__ void es_scan_kernel(const float* __restrict__ x,
                               const float* __restrict__ lvl_coef,
                               const float* __restrict__ seas_coef,
                               const float* __restrict__ seas_params) {
    const int lane = threadIdx.x;
    const unsigned FULL = 0xFFFFFFFFu;
    for (int i = lane; i < SEAS; i += 32) g_wall[i] = expf(seas_params[i]);
    __syncwarp();
    if (lane == 0) g_wall[SEAS] = g_wall[0];
    __syncwarp();

    const float a = 1.0f / (1.0f + expf(-lvl_coef[0]));
    const float g = 1.0f / (1.0f + expf(-seas_coef[0]));
    const float b = 1.0f - a;
    const float omg = 1.0f - g;
    const float b5 = b * b * b * b * b;
    const float bl = __powf(b5, (float)lane);   // b^(5*lane)

    float level = x[0] / g_wall[0];
    if (lane == 0) g_levels[0] = level;

    for (int t0 = 1; t0 < T_LEN; t0 += CHUNK) {
        const int base = t0 + lane * LPL;
        float xi[LPL], se[LPL], c[LPL];
#pragma unroll
        for (int j = 0; j < LPL; j++) {
            int t = base + j;
            if (t < T_LEN) {
                xi[j] = x[t];
                se[j] = g_wall[t];
                c[j]  = __fdividef(a * xi[j], se[j]);
            } else { xi[j] = 1.0f; se[j] = 1.0f; c[j] = 0.0f; }
        }
        float s = 0.0f;
#pragma unroll
        for (int j = 0; j < LPL; j++) s = fmaf(b, s, c[j]);
        float S = s;
        float m = b5;
#pragma unroll
        for (int off = 1; off < 32; off <<= 1) {
            float up = __shfl_up_sync(FULL, S, off);
            if (lane >= off) S = fmaf(m, up, S);
            m = m * m;
        }
        float Sprev = __shfl_up_sync(FULL, S, 1);
        if (lane == 0) Sprev = 0.0f;
        float lvl = fmaf(bl, level, Sprev);
#pragma unroll
        for (int j = 0; j < LPL; j++) {
            int t = base + j;
            if (t < T_LEN) {
                lvl = fmaf(b, lvl, c[j]);
                g_levels[t] = lvl;
                float ns = fmaf(omg, se[j], __fdividef(g * xi[j], lvl));
                if (t + SEAS < T_LEN) g_wall[t + SEAS] = ns;
            }
        }
        level = __shfl_sync(FULL, lvl, 31);
        __syncwarp();
    }
}

// ---------------- parallel log precompute ----------------
__global__ void prep_kernel(const float* __restrict__ x) {
    int i = blockIdx.x * blockDim.x + threadIdx.x;
    if (i < T_LEN) {
        g_llev[i] = logf(g_levels[i]);
        g_c[i]    = logf(x[i]) - logf(g_wall[i]);
    }
}

// ---------------- level variation loss ----------------
__global__ void loss_kernel(float* __restrict__ d_out) {
    __shared__ double sh[256];
    double acc = 0.0;
    for (int i = threadIdx.x; i < T_LEN - 2; i += 256) {
        float d2 = (g_llev[i + 2] - g_llev[i + 1]) - (g_llev[i + 1] - g_llev[i]);
        acc += (double)d2 * (double)d2;
    }
    sh[threadIdx.x] = acc;
    __syncthreads();
    for (int s = 128; s > 0; s >>= 1) {
        if (threadIdx.x < s) sh[threadIdx.x] += sh[threadIdx.x + s];
        __syncthreads();
    }
    if (threadIdx.x == 0)
        d_out[2 * (size_t)N_ROWS * OUTSZ] = (float)(sh[0] / (double)(T_LEN - 2) * (double)LVP_F);
}

// ---------------- inputs matrix: c[n+w] - L[n] + 0.001*z (4 elems/thread) ----------------
__global__ void gen_inputs_kernel() {
    constexpr TF2 K1 = tf2x32_const(0u, 1u, 0u, 0u);   // split(key(1))[0]
    const unsigned M = (unsigned)N_ROWS * WIN;          // divisible by 4
    unsigned t = blockIdx.x * blockDim.x + threadIdx.x;
    unsigned i0 = 4u * t;
    if (i0 >= M) return;
    float v[4];
#pragma unroll
    for (int j = 0; j < 4; j++) {
        unsigned i = i0 + j;
        unsigned n = i / WIN, w = i - n * WIN;
        float z = bits_to_normal(tf_bits32(K1.y0, K1.y1, i));
        v[j] = g_c[n + w] - g_llev[n + WIN] + STD_NOISE * z;
    }
    *reinterpret_cast<float4*>(&g_inputs[i0]) = make_float4(v[0], v[1], v[2], v[3]);
}

// ---------------- labels directly into d_out (4 elems/thread) ----------------
__global__ void gen_labels_kernel(float* __restrict__ d_out) {
    constexpr TF2 K2 = tf2x32_const(0u, 1u, 0u, 1u);   // split(key(1))[1]
    const unsigned M = (unsigned)N_ROWS * OUTSZ;        // divisible by 4
    unsigned t = blockIdx.x * blockDim.x + threadIdx.x;
    unsigned i0 = 4u * t;
    if (i0 >= M) return;
    float* labels = d_out + (size_t)N_ROWS * OUTSZ;
    float v[4];
#pragma unroll
    for (int j = 0; j < 4; j++) {
        unsigned i = i0 + j;
        unsigned n = i / OUTSZ, o = i - n * OUTSZ;
        float z = bits_to_normal(tf_bits32(K2.y0, K2.y1, i));
        v[j] = g_c[n + WIN + o] - g_llev[n + WIN] + STD_NOISE * z;
    }
    *reinterpret_cast<float4*>(&labels[i0]) = make_float4(v[0], v[1], v[2], v[3]);
}

// ---------------- fp32x2 packed-FFMA GEMM (+optional tanh epilogue) ----------------
// A tile stored DUPLICATED in shared: As2[k][2m]=As2[k][2m+1]=A[m][k], so one
// LDS.128 yields two packed (a_i,a_i) 64-bit operands for fma.rn.f32x2.
template<int BM, int BN, int BK, int TM, int TN, int NTHREADS, bool DO_TANH>
__global__ void __launch_bounds__(NTHREADS)
sgemm_f32x2_kernel(const float* __restrict__ A, const float* __restrict__ B,
                   const float* __restrict__ bias, float* __restrict__ C,
                   int M, int K, int Ncol) {
    __shared__ float As2[BK][2 * BM];
    __shared__ float Bs[BK][BN];
    const int tid = threadIdx.x;
    const int tx  = tid % (BN / TN);
    const int ty  = tid / (BN / TN);
    const int row0 = blockIdx.x * BM;
    const int col0 = blockIdx.y * BN;

    unsigned long long acc[TM][TN / 2];
#pragma unroll
    for (int i = 0; i < TM; i++)
#pragma unroll
        for (int j = 0; j < TN / 2; j++) acc[i][j] = 0ull;

    for (int k0 = 0; k0 < K; k0 += BK) {
        for (int i = tid; i < BM * BK; i += NTHREADS) {
            int r = i / BK, kk = i % BK;
            int gr = row0 + r;
            float v = (gr < M) ? A[(size_t)gr * K + (k0 + kk)] : 0.0f;
            As2[kk][2 * r]     = v;
            As2[kk][2 * r + 1] = v;
        }
        for (int i = tid; i < BK * BN; i += NTHREADS) {
            int kk = i / BN, c = i % BN;
            int gc = col0 + c;
            Bs[kk][c] = (gc < Ncol) ? B[(size_t)(k0 + kk) * Ncol + gc] : 0.0f;
        }
        __syncthreads();
#pragma unroll
        for (int kk = 0; kk < BK; kk++) {
            unsigned long long aa[TM];
            const ulonglong2* ap =
                reinterpret_cast<const ulonglong2*>(&As2[kk][2 * (ty * TM)]);
#pragma unroll
            for (int i = 0; i < TM / 2; i++) {
                ulonglong2 v = ap[i];
                aa[2 * i] = v.x; aa[2 * i + 1] = v.y;
            }
            unsigned long long bb[TN / 2];
            const ulonglong2* bp =
                reinterpret_cast<const ulonglong2*>(&Bs[kk][tx * TN]);
#pragma unroll
            for (int j = 0; j < TN / 4; j++) {
                ulonglong2 v = bp[j];
                bb[2 * j] = v.x; bb[2 * j + 1] = v.y;
            }
#pragma unroll
            for (int i = 0; i < TM; i++)
#pragma unroll
                for (int j = 0; j < TN / 2; j++)
                    asm("fma.rn.f32x2 %0, %1, %2, %0;"
                        : "+l"(acc[i][j]) : "l"(aa[i]), "l"(bb[j]));
        }
        __syncthreads();
    }

#pragma unroll
    for (int i = 0; i < TM; i++) {
        int gr = row0 + ty * TM + i;
        if (gr >= M) continue;
#pragma unroll
        for (int j = 0; j < TN / 2; j++) {
            union { unsigned long long u; float2 f; } cvt;
            cvt.u = acc[i][j];
            int gc0 = col0 + tx * TN + 2 * j;
            if (gc0 < Ncol) {
                float v = cvt.f.x + bias[gc0];
                C[(size_t)gr * Ncol + gc0] = DO_TANH ? tanhf(v) : v;
            }
            if (gc0 + 1 < Ncol) {
                float v = cvt.f.y + bias[gc0 + 1];
                C[(size_t)gr * Ncol + gc0 + 1] = DO_TANH ? tanhf(v) : v;
            }
        }
    }
}

// ---------------- launch ----------------
extern "C" void kernel_launch(void* const* d_in, const int* in_sizes, int n_in,
                              void* d_out, int out_size) {
    const float* x           = (const float*)d_in[0];
    const float* lvl_coef    = (const float*)d_in[1];
    const float* seas_coef   = (const float*)d_in[2];
    const float* seas_params = (const float*)d_in[3];
    const float* W_tanh      = (const float*)d_in[4];
    const float* b_tanh      = (const float*)d_in[5];
    const float* W_out       = (const float*)d_in[6];
    const float* b_out       = (const float*)d_in[7];
    float* out = (float*)d_out;

    void *p_inputs = nullptr, *p_hidden = nullptr;
    cudaGetSymbolAddress(&p_inputs, g_inputs);
    cudaGetSymbolAddress(&p_hidden, g_hidden);
    float* inputs = (float*)p_inputs;
    float* hidden = (float*)p_hidden;

    es_scan_kernel<<<1, 32>>>(x, lvl_coef, seas_coef, seas_params);
    prep_kernel<<<(T_LEN + 255) / 256, 256>>>(x);
    loss_kernel<<<1, 256>>>(out);

    {
        unsigned P = ((unsigned)N_ROWS * WIN) / 4u;
        gen_inputs_kernel<<<(P + 255) / 256, 256>>>();
    }
    {
        unsigned P = ((unsigned)N_ROWS * OUTSZ) / 4u;
        gen_labels_kernel<<<(P + 255) / 256, 256>>>(out);
    }

    // hidden = tanh(inputs @ W_tanh + b_tanh): [N,336]x[336,336]
    {
        dim3 grid((N_ROWS + 127) / 128, (WIN + 127) / 128);
        sgemm_f32x2_kernel<128, 128, 8, 8, 8, 256, true><<<grid, 256>>>(
            inputs, W_tanh, b_tanh, hidden, N_ROWS, WIN, WIN);
    }
    // out = hidden @ W_out + b_out: [N,336]x[336,48]
    {
        dim3 grid((N_ROWS + 127) / 128, 1);
        sgemm_f32x2_kernel<128, 64, 8, 8, 8, 128, false><<<grid, 128>>>(
            hidden, W_out, b_out, out, N_ROWS, WIN, OUTSZ);
    }
    (void)in_sizes; (void)n_in; (void)out_size;
}

// round 7
// speedup vs baseline: 1.9748x; 1.9748x over previous
#include <cuda_runtime.h>
#include <cuda_bf16.h>
#include <math.h>

#define T_LEN 100000
#define WIN   336
#define OUTSZ 48
#define SEAS  168
#define N_ROWS (T_LEN - WIN - OUTSZ + 1)   // 99617
#define M_PAD  99712                        // 779 * 128
#define STD_NOISE 0.001f
#define LVP_F 50.0f
#define CHUNK 160
#define LPL 5

#define G1_SMEM 62976
#define G2_SMEM 50688

// ---------------- device scratch ----------------
__device__ float g_levels[T_LEN];
__device__ float g_wall[T_LEN];
__device__ float g_llev[T_LEN];
__device__ float g_c[T_LEN];
__device__ __nv_bfloat16 g_a_hi[(size_t)M_PAD * WIN];
__device__ __nv_bfloat16 g_a_lo[(size_t)M_PAD * WIN];
__device__ __nv_bfloat16 g_h_hi[(size_t)M_PAD * WIN];
__device__ __nv_bfloat16 g_h_lo[(size_t)M_PAD * WIN];
__device__ __nv_bfloat16 g_w1h[WIN * WIN], g_w1l[WIN * WIN];
__device__ __nv_bfloat16 g_w2h[WIN * OUTSZ], g_w2l[WIN * OUTSZ];

// ---------------- compile-time threefry ----------------
struct TF2 { unsigned y0, y1; };
__host__ __device__ constexpr unsigned tf_rotl(unsigned x, int r) {
    return (x << r) | (x >> (32 - r));
}
__host__ __device__ constexpr TF2 tf2x32_const(unsigned k0, unsigned k1,
                                               unsigned x0, unsigned x1) {
    unsigned ks2 = 0x1BD11BDAu ^ k0 ^ k1;
    const int R[8] = {13, 15, 26, 6, 17, 29, 16, 24};
    x0 += k0; x1 += k1;
    for (int i = 0; i < 4; i++) { x0 += x1; x1 = tf_rotl(x1, R[i]); x1 ^= x0; }
    x0 += k1;  x1 += ks2 + 1u;
    for (int i = 4; i < 8; i++) { x0 += x1; x1 = tf_rotl(x1, R[i]); x1 ^= x0; }
    x0 += ks2; x1 += k0 + 2u;
    for (int i = 0; i < 4; i++) { x0 += x1; x1 = tf_rotl(x1, R[i]); x1 ^= x0; }
    x0 += k0;  x1 += k1 + 3u;
    for (int i = 4; i < 8; i++) { x0 += x1; x1 = tf_rotl(x1, R[i]); x1 ^= x0; }
    x0 += k1;  x1 += ks2 + 4u;
    for (int i = 0; i < 4; i++) { x0 += x1; x1 = tf_rotl(x1, R[i]); x1 ^= x0; }
    x0 += ks2; x1 += k0 + 5u;
    return TF2{x0, x1};
}

// ---------------- runtime threefry2x32 (JAX partitionable) ----------------
__device__ __forceinline__ void threefry2x32(unsigned k0, unsigned k1,
                                             unsigned x0, unsigned x1,
                                             unsigned& y0, unsigned& y1) {
    unsigned ks2 = 0x1BD11BDAu ^ k0 ^ k1;
#define TF_RND(r) { x0 += x1; x1 = (x1 << (r)) | (x1 >> (32 - (r))); x1 ^= x0; }
    x0 += k0; x1 += k1;
    TF_RND(13) TF_RND(15) TF_RND(26) TF_RND(6)
    x0 += k1;  x1 += ks2 + 1u;
    TF_RND(17) TF_RND(29) TF_RND(16) TF_RND(24)
    x0 += ks2; x1 += k0 + 2u;
    TF_RND(13) TF_RND(15) TF_RND(26) TF_RND(6)
    x0 += k0;  x1 += k1 + 3u;
    TF_RND(17) TF_RND(29) TF_RND(16) TF_RND(24)
    x0 += k1;  x1 += ks2 + 4u;
    TF_RND(13) TF_RND(15) TF_RND(26) TF_RND(6)
    x0 += ks2; x1 += k0 + 5u;
#undef TF_RND
    y0 = x0; y1 = x1;
}
__device__ __forceinline__ unsigned tf_bits32(unsigned k0, unsigned k1, unsigned i) {
    unsigned y0, y1;
    threefry2x32(k0, k1, 0u, i, y0, y1);
    return y0 ^ y1;
}

__device__ __forceinline__ float bits_to_normal(unsigned bits) {
    float f = __uint_as_float((bits >> 9) | 0x3f800000u) - 1.0f;
    const float LO = -0.99999994f;
    float u = fmaxf(LO, f * 2.0f + LO);
    float x = u;
    float w = -log1pf(-x * x);
    float p;
    if (w < 5.0f) {
        w -= 2.5f;
        p =              2.81022636e-08f;
        p = fmaf(p, w,   3.43273939e-07f);
        p = fmaf(p, w,  -3.5233877e-06f);
        p = fmaf(p, w,  -4.39150654e-06f);
        p = fmaf(p, w,   0.00021858087f);
        p = fmaf(p, w,  -0.00125372503f);
        p = fmaf(p, w,  -0.00417768164f);
        p = fmaf(p, w,   0.246640727f);
        p = fmaf(p, w,   1.50140941f);
    } else {
        w = sqrtf(w) - 3.0f;
        p =             -0.000200214257f;
        p = fmaf(p, w,   0.000100950558f);
        p = fmaf(p, w,   0.00134934322f);
        p = fmaf(p, w,  -0.00367342844f);
        p = fmaf(p, w,   0.00573950773f);
        p = fmaf(p, w,  -0.0076224613f);
        p = fmaf(p, w,   0.00943887047f);
        p = fmaf(p, w,   1.00167406f);
        p = fmaf(p, w,   2.83297682f);
    }
    return 1.41421356237f * (p * x);
}

// ---------------- warp-parallel chunked ES scan ----------------
__global__ void es_scan_kernel(const float* __restrict__ x,
                               const float* __restrict__ lvl_coef,
                               const float* __restrict__ seas_coef,
                               const float* __restrict__ seas_params) {
    const int lane = threadIdx.x;
    const unsigned FULL = 0xFFFFFFFFu;
    for (int i = lane; i < SEAS; i += 32) g_wall[i] = expf(seas_params[i]);
    __syncwarp();
    if (lane == 0) g_wall[SEAS] = g_wall[0];
    __syncwarp();

    const float a = 1.0f / (1.0f + expf(-lvl_coef[0]));
    const float g = 1.0f / (1.0f + expf(-seas_coef[0]));
    const float b = 1.0f - a;
    const float omg = 1.0f - g;
    const float b5 = b * b * b * b * b;
    const float bl = __powf(b5, (float)lane);

    float level = x[0] / g_wall[0];
    if (lane == 0) g_levels[0] = level;

    for (int t0 = 1; t0 < T_LEN; t0 += CHUNK) {
        const int base = t0 + lane * LPL;
        float xi[LPL], se[LPL], c[LPL];
#pragma unroll
        for (int j = 0; j < LPL; j++) {
            int t = base + j;
            if (t < T_LEN) {
                xi[j] = x[t];
                se[j] = g_wall[t];
                c[j]  = __fdividef(a * xi[j], se[j]);
            } else { xi[j] = 1.0f; se[j] = 1.0f; c[j] = 0.0f; }
        }
        float s = 0.0f;
#pragma unroll
        for (int j = 0; j < LPL; j++) s = fmaf(b, s, c[j]);
        float S = s;
        float m = b5;
#pragma unroll
        for (int off = 1; off < 32; off <<= 1) {
            float up = __shfl_up_sync(FULL, S, off);
            if (lane >= off) S = fmaf(m, up, S);
            m = m * m;
        }
        float Sprev = __shfl_up_sync(FULL, S, 1);
        if (lane == 0) Sprev = 0.0f;
        float lvl = fmaf(bl, level, Sprev);
#pragma unroll
        for (int j = 0; j < LPL; j++) {
            int t = base + j;
            if (t < T_LEN) {
                lvl = fmaf(b, lvl, c[j]);
                g_levels[t] = lvl;
                float ns = fmaf(omg, se[j], __fdividef(g * xi[j], lvl));
                if (t + SEAS < T_LEN) g_wall[t + SEAS] = ns;
            }
        }
        level = __shfl_sync(FULL, lvl, 31);
        __syncwarp();
    }
}

// ---------------- parallel log precompute ----------------
__global__ void prep_kernel(const float* __restrict__ x) {
    int i = blockIdx.x * blockDim.x + threadIdx.x;
    if (i < T_LEN) {
        g_llev[i] = logf(g_levels[i]);
        g_c[i]    = logf(x[i]) - logf(g_wall[i]);
    }
}

// ---------------- level variation loss ----------------
__global__ void loss_kernel(float* __restrict__ d_out) {
    __shared__ double sh[256];
    double acc = 0.0;
    for (int i = threadIdx.x; i < T_LEN - 2; i += 256) {
        float d2 = (g_llev[i + 2] - g_llev[i + 1]) - (g_llev[i + 1] - g_llev[i]);
        acc += (double)d2 * (double)d2;
    }
    sh[threadIdx.x] = acc;
    __syncthreads();
    for (int s = 128; s > 0; s >>= 1) {
        if (threadIdx.x < s) sh[threadIdx.x] += sh[threadIdx.x + s];
        __syncthreads();
    }
    if (threadIdx.x == 0)
        d_out[2 * (size_t)N_ROWS * OUTSZ] = (float)(sh[0] / (double)(T_LEN - 2) * (double)LVP_F);
}

// ---------------- split helpers ----------------
__device__ __forceinline__ void split_bf16(float v, __nv_bfloat16& hi, __nv_bfloat16& lo) {
    hi = __float2bfloat16(v);
    lo = __float2bfloat16(v - __bfloat162float(hi));
}

// ---------------- inputs matrix -> bf16 hi/lo (4 elems/thread) ----------------
__global__ void gen_inputs_kernel() {
    constexpr TF2 K1 = tf2x32_const(0u, 1u, 0u, 0u);
    const unsigned M = (unsigned)N_ROWS * WIN;
    unsigned t = blockIdx.x * blockDim.x + threadIdx.x;
    unsigned i0 = 4u * t;
    if (i0 >= M) return;
    __nv_bfloat16 hi[4], lo[4];
#pragma unroll
    for (int j = 0; j < 4; j++) {
        unsigned i = i0 + j;
        unsigned n = i / WIN, w = i - n * WIN;
        float z = bits_to_normal(tf_bits32(K1.y0, K1.y1, i));
        float v = g_c[n + w] - g_llev[n + WIN] + STD_NOISE * z;
        split_bf16(v, hi[j], lo[j]);
    }
    *reinterpret_cast<__nv_bfloat162*>(&g_a_hi[i0])     = __nv_bfloat162{hi[0], hi[1]};
    *reinterpret_cast<__nv_bfloat162*>(&g_a_hi[i0 + 2]) = __nv_bfloat162{hi[2], hi[3]};
    *reinterpret_cast<__nv_bfloat162*>(&g_a_lo[i0])     = __nv_bfloat162{lo[0], lo[1]};
    *reinterpret_cast<__nv_bfloat162*>(&g_a_lo[i0 + 2]) = __nv_bfloat162{lo[2], lo[3]};
}

// zero tail rows [N_ROWS*WIN, M_PAD*WIN)
__global__ void zero_tail_kernel() {
    const unsigned start = (unsigned)N_ROWS * WIN;
    const unsigned total = (unsigned)M_PAD * WIN - start;
    unsigned i = blockIdx.x * blockDim.x + threadIdx.x;
    if (i < total) {
        g_a_hi[start + i] = __float2bfloat16(0.0f);
        g_a_lo[start + i] = __float2bfloat16(0.0f);
    }
}

// split weights
__global__ void wsplit_kernel(const float* __restrict__ W1, const float* __restrict__ W2) {
    int i = blockIdx.x * blockDim.x + threadIdx.x;
    if (i < WIN * WIN) split_bf16(W1[i], g_w1h[i], g_w1l[i]);
    if (i < WIN * OUTSZ) split_bf16(W2[i], g_w2h[i], g_w2l[i]);
}

// ---------------- labels directly into d_out ----------------
__global__ void gen_labels_kernel(float* __restrict__ d_out) {
    constexpr TF2 K2 = tf2x32_const(0u, 1u, 0u, 1u);
    const unsigned M = (unsigned)N_ROWS * OUTSZ;
    unsigned t = blockIdx.x * blockDim.x + threadIdx.x;
    unsigned i0 = 4u * t;
    if (i0 >= M) return;
    float* labels = d_out + (size_t)N_ROWS * OUTSZ;
    float v[4];
#pragma unroll
    for (int j = 0; j < 4; j++) {
        unsigned i = i0 + j;
        unsigned n = i / OUTSZ, o = i - n * OUTSZ;
        float z = bits_to_normal(tf_bits32(K2.y0, K2.y1, i));
        v[j] = g_c[n + WIN + o] - g_llev[n + WIN] + STD_NOISE * z;
    }
    *reinterpret_cast<float4*>(&labels[i0]) = make_float4(v[0], v[1], v[2], v[3]);
}

// ---------------- mma helpers ----------------
__device__ __forceinline__ unsigned sm_u32(const void* p) {
    return (unsigned)__cvta_generic_to_shared(p);
}
__device__ __forceinline__ void ldsm_x4(unsigned* d, unsigned addr) {
    asm volatile("ldmatrix.sync.aligned.m8n8.x4.shared.b16 {%0,%1,%2,%3}, [%4];"
                 : "=r"(d[0]), "=r"(d[1]), "=r"(d[2]), "=r"(d[3]) : "r"(addr));
}
__device__ __forceinline__ void ldsm_x4t(unsigned* d, unsigned addr) {
    asm volatile("ldmatrix.sync.aligned.m8n8.x4.trans.shared.b16 {%0,%1,%2,%3}, [%4];"
                 : "=r"(d[0]), "=r"(d[1]), "=r"(d[2]), "=r"(d[3]) : "r"(addr));
}
__device__ __forceinline__ void mma16816(float* c, const unsigned* a, unsigned b0, unsigned b1) {
    asm volatile("mma.sync.aligned.m16n8k16.row.col.f32.bf16.bf16.f32 "
                 "{%0,%1,%2,%3}, {%4,%5,%6,%7}, {%8,%9}, {%0,%1,%2,%3};"
                 : "+f"(c[0]), "+f"(c[1]), "+f"(c[2]), "+f"(c[3])
                 : "r"(a[0]), "r"(a[1]), "r"(a[2]), "r"(a[3]), "r"(b0), "r"(b1));
}

// ---------------- GEMM1: hidden = tanh(A@W1 + b1), 3-term bf16 split ----------------
// BM=128, BN=128 (N=336 masked), BK=48, 8 warps as 2m x 4n, warp tile 64x32.
#define G1_AST 72    // A smem stride (bf16)
#define G1_BST 136   // B smem stride (bf16)
__global__ void __launch_bounds__(256, 2)
gemm1_kernel(const float* __restrict__ bias) {
    extern __shared__ char smem[];
    __nv_bfloat16* sAh = (__nv_bfloat16*)(smem);
    __nv_bfloat16* sAl = (__nv_bfloat16*)(smem + 18432);
    __nv_bfloat16* sBh = (__nv_bfloat16*)(smem + 36864);
    __nv_bfloat16* sBl = (__nv_bfloat16*)(smem + 49920);

    const int tid = threadIdx.x;
    const int wid = tid >> 5, lane = tid & 31;
    const int wm = wid >> 2, wn = wid & 3;
    const int row0 = blockIdx.x * 128;
    const int col0 = blockIdx.y * 128;
    const int lrow = lane & 15, lcol = (lane >> 4) << 3;

    float acc[4][4][4];
#pragma unroll
    for (int i = 0; i < 4; i++)
#pragma unroll
        for (int j = 0; j < 4; j++)
#pragma unroll
            for (int k = 0; k < 4; k++) acc[i][j][k] = 0.0f;

    for (int k0 = 0; k0 < WIN; k0 += 48) {
        for (int idx = tid; idx < 128 * 6; idx += 256) {
            int r = idx / 6, cb = (idx % 6) * 8;
            size_t go = (size_t)(row0 + r) * WIN + k0 + cb;
            *(uint4*)&sAh[r * G1_AST + cb] = *(const uint4*)&g_a_hi[go];
            *(uint4*)&sAl[r * G1_AST + cb] = *(const uint4*)&g_a_lo[go];
        }
        for (int idx = tid; idx < 48 * 16; idx += 256) {
            int r = idx / 16, cb = (idx % 16) * 8;
            int gn = col0 + cb;
            uint4 vh = make_uint4(0, 0, 0, 0), vl = vh;
            if (gn < WIN) {
                size_t go = (size_t)(k0 + r) * WIN + gn;
                vh = *(const uint4*)&g_w1h[go];
                vl = *(const uint4*)&g_w1l[go];
            }
            *(uint4*)&sBh[r * G1_BST + cb] = vh;
            *(uint4*)&sBl[r * G1_BST + cb] = vl;
        }
        __syncthreads();
#pragma unroll
        for (int ks = 0; ks < 3; ks++) {
            unsigned bh[2][4], bl[2][4];
#pragma unroll
            for (int nf2 = 0; nf2 < 2; nf2++) {
                unsigned addr = sm_u32(&sBh[(ks * 16 + lrow) * G1_BST + wn * 32 + nf2 * 16 + lcol]);
                ldsm_x4t(bh[nf2], addr);
                addr = sm_u32(&sBl[(ks * 16 + lrow) * G1_BST + wn * 32 + nf2 * 16 + lcol]);
                ldsm_x4t(bl[nf2], addr);
            }
#pragma unroll
            for (int mf = 0; mf < 4; mf++) {
                unsigned ah[4], al[4];
                unsigned addr = sm_u32(&sAh[(wm * 64 + mf * 16 + lrow) * G1_AST + ks * 16 + lcol]);
                ldsm_x4(ah, addr);
                addr = sm_u32(&sAl[(wm * 64 + mf * 16 + lrow) * G1_AST + ks * 16 + lcol]);
                ldsm_x4(al, addr);
#pragma unroll
                for (int nf2 = 0; nf2 < 2; nf2++) {
#pragma unroll
                    for (int h = 0; h < 2; h++) {
                        int n8 = nf2 * 2 + h;
                        mma16816(acc[mf][n8], ah, bh[nf2][2 * h], bh[nf2][2 * h + 1]);
                        mma16816(acc[mf][n8], al, bh[nf2][2 * h], bh[nf2][2 * h + 1]);
                        mma16816(acc[mf][n8], ah, bl[nf2][2 * h], bl[nf2][2 * h + 1]);
                    }
                }
            }
        }
        __syncthreads();
    }

    const int group = lane >> 2, tig = lane & 3;
#pragma unroll
    for (int mf = 0; mf < 4; mf++) {
#pragma unroll
        for (int n8 = 0; n8 < 4; n8++) {
            int gc = col0 + wn * 32 + n8 * 8 + 2 * tig;
            if (gc >= WIN) continue;
            float b0 = bias[gc], b1 = bias[gc + 1];
            int r0 = row0 + wm * 64 + mf * 16 + group;
#pragma unroll
            for (int half = 0; half < 2; half++) {
                int gr = r0 + half * 8;
                float t0 = tanhf(acc[mf][n8][2 * half] + b0);
                float t1 = tanhf(acc[mf][n8][2 * half + 1] + b1);
                __nv_bfloat16 h0, l0, h1, l1;
                split_bf16(t0, h0, l0);
                split_bf16(t1, h1, l1);
                size_t go = (size_t)gr * WIN + gc;
                *reinterpret_cast<__nv_bfloat162*>(&g_h_hi[go]) = __nv_bfloat162{h0, h1};
                *reinterpret_cast<__nv_bfloat162*>(&g_h_lo[go]) = __nv_bfloat162{l0, l1};
            }
        }
    }
}

// ---------------- GEMM2: out = hidden@W2 + b2, 3-term bf16 split ----------------
// BM=128, BN=48, BK=48. 8 warps as 8m x 1n, warp tile 16x48.
#define G2_BST 72
__global__ void __launch_bounds__(256, 2)
gemm2_kernel(const float* __restrict__ bias, float* __restrict__ out) {
    extern __shared__ char smem[];
    __nv_bfloat16* sAh = (__nv_bfloat16*)(smem);
    __nv_bfloat16* sAl = (__nv_bfloat16*)(smem + 18432);
    __nv_bfloat16* sBh = (__nv_bfloat16*)(smem + 36864);
    __nv_bfloat16* sBl = (__nv_bfloat16*)(smem + 43776);

    const int tid = threadIdx.x;
    const int wid = tid >> 5, lane = tid & 31;
    const int row0 = blockIdx.x * 128;
    const int lrow = lane & 15, lcol = (lane >> 4) << 3;

    float acc[6][4];
#pragma unroll
    for (int i = 0; i < 6; i++)
#pragma unroll
        for (int k = 0; k < 4; k++) acc[i][k] = 0.0f;

    for (int k0 = 0; k0 < WIN; k0 += 48) {
        for (int idx = tid; idx < 128 * 6; idx += 256) {
            int r = idx / 6, cb = (idx % 6) * 8;
            size_t go = (size_t)(row0 + r) * WIN + k0 + cb;
            *(uint4*)&sAh[r * G1_AST + cb] = *(const uint4*)&g_h_hi[go];
            *(uint4*)&sAl[r * G1_AST + cb] = *(const uint4*)&g_h_lo[go];
        }
        for (int idx = tid; idx < 48 * 6; idx += 256) {
            int r = idx / 6, cb = (idx % 6) * 8;
            size_t go = (size_t)(k0 + r) * OUTSZ + cb;
            *(uint4*)&sBh[r * G2_BST + cb] = *(const uint4*)&g_w2h[go];
            *(uint4*)&sBl[r * G2_BST + cb] = *(const uint4*)&g_w2l[go];
        }
        __syncthreads();
#pragma unroll
        for (int ks = 0; ks < 3; ks++) {
            unsigned ah[4], al[4];
            unsigned addr = sm_u32(&sAh[(wid * 16 + lrow) * G1_AST + ks * 16 + lcol]);
            ldsm_x4(ah, addr);
            addr = sm_u32(&sAl[(wid * 16 + lrow) * G1_AST + ks * 16 + lcol]);
            ldsm_x4(al, addr);
#pragma unroll
            for (int nf2 = 0; nf2 < 3; nf2++) {
                unsigned bh[4], bl[4];
                addr = sm_u32(&sBh[(ks * 16 + lrow) * G2_BST + nf2 * 16 + lcol]);
                ldsm_x4t(bh, addr);
                addr = sm_u32(&sBl[(ks * 16 + lrow) * G2_BST + nf2 * 16 + lcol]);
                ldsm_x4t(bl, addr);
#pragma unroll
                for (int h = 0; h < 2; h++) {
                    int n8 = nf2 * 2 + h;
                    mma16816(acc[n8], ah, bh[2 * h], bh[2 * h + 1]);
                    mma16816(acc[n8], al, bh[2 * h], bh[2 * h + 1]);
                    mma16816(acc[n8], ah, bl[2 * h], bl[2 * h + 1]);
                }
            }
        }
        __syncthreads();
    }

    const int group = lane >> 2, tig = lane & 3;
#pragma unroll
    for (int n8 = 0; n8 < 6; n8++) {
        int gc = n8 * 8 + 2 * tig;
        float b0 = bias[gc], b1 = bias[gc + 1];
        int r0 = row0 + wid * 16 + group;
#pragma unroll
        for (int half = 0; half < 2; half++) {
            int gr = r0 + half * 8;
            if (gr < N_ROWS) {
                float2 v = make_float2(acc[n8][2 * half] + b0, acc[n8][2 * half + 1] + b1);
                *reinterpret_cast<float2*>(&out[(size_t)gr * OUTSZ + gc]) = v;
            }
        }
    }
}

// ---------------- launch ----------------
extern "C" void kernel_launch(void* const* d_in, const int* in_sizes, int n_in,
                              void* d_out, int out_size) {
    const float* x           = (const float*)d_in[0];
    const float* lvl_coef    = (const float*)d_in[1];
    const float* seas_coef   = (const float*)d_in[2];
    const float* seas_params = (const float*)d_in[3];
    const float* W_tanh      = (const float*)d_in[4];
    const float* b_tanh      = (const float*)d_in[5];
    const float* W_out       = (const float*)d_in[6];
    const float* b_out       = (const float*)d_in[7];
    float* out = (float*)d_out;

    cudaFuncSetAttribute(gemm1_kernel, cudaFuncAttributeMaxDynamicSharedMemorySize, G1_SMEM);
    cudaFuncSetAttribute(gemm2_kernel, cudaFuncAttributeMaxDynamicSharedMemorySize, G2_SMEM);

    es_scan_kernel<<<1, 32>>>(x, lvl_coef, seas_coef, seas_params);
    prep_kernel<<<(T_LEN + 255) / 256, 256>>>(x);
    loss_kernel<<<1, 256>>>(out);
    wsplit_kernel<<<(WIN * WIN + 255) / 256, 256>>>(W_tanh, W_out);
    zero_tail_kernel<<<((M_PAD - N_ROWS) * WIN + 255) / 256, 256>>>();

    {
        unsigned P = ((unsigned)N_ROWS * WIN) / 4u;
        gen_inputs_kernel<<<(P + 255) / 256, 256>>>();
    }
    {
        unsigned P = ((unsigned)N_ROWS * OUTSZ) / 4u;
        gen_labels_kernel<<<(P + 255) / 256, 256>>>(out);
    }

    {
        dim3 grid(M_PAD / 128, 3);
        gemm1_kernel<<<grid, 256, G1_SMEM>>>(b_tanh);
    }
    {
        dim3 grid(M_PAD / 128);
        gemm2_kernel<<<grid, 256, G2_SMEM>>>(b_out, out);
    }
    (void)in_sizes; (void)n_in; (void)out_size;
}

// round 9
// speedup vs baseline: 2.1130x; 1.0700x over previous
#include <cuda_runtime.h>
#include <cuda_bf16.h>
#include <math.h>

#define T_LEN 100000
#define WIN   336
#define OUTSZ 48
#define SEAS  168
#define N_ROWS (T_LEN - WIN - OUTSZ + 1)   // 99617
#define M_PAD  99712                        // 779 * 128
#define STD_NOISE 0.001f
#define LVP_F 50.0f
#define CHUNK 160
#define LPL 5

#define G1_STAGE 62976
#define G1_SMEM  (2 * G1_STAGE)            // 125952
#define G2_STAGE 50688
#define G2_SMEM  (2 * G2_STAGE)            // 101376

// ---------------- device scratch ----------------
__device__ float g_levels[T_LEN];
__device__ float g_wall[T_LEN];
__device__ float g_llev[T_LEN];
__device__ float g_c[T_LEN];
__device__ __nv_bfloat16 g_a_hi[(size_t)M_PAD * WIN];
__device__ __nv_bfloat16 g_a_lo[(size_t)M_PAD * WIN];
__device__ __nv_bfloat16 g_h_hi[(size_t)M_PAD * WIN];
__device__ __nv_bfloat16 g_h_lo[(size_t)M_PAD * WIN];
__device__ __nv_bfloat16 g_w1h[WIN * WIN], g_w1l[WIN * WIN];
__device__ __nv_bfloat16 g_w2h[WIN * OUTSZ], g_w2l[WIN * OUTSZ];

// ---------------- compile-time threefry ----------------
struct TF2 { unsigned y0, y1; };
__host__ __device__ constexpr unsigned tf_rotl(unsigned x, int r) {
    return (x << r) | (x >> (32 - r));
}
__host__ __device__ constexpr TF2 tf2x32_const(unsigned k0, unsigned k1,
                                               unsigned x0, unsigned x1) {
    unsigned ks2 = 0x1BD11BDAu ^ k0 ^ k1;
    const int R[8] = {13, 15, 26, 6, 17, 29, 16, 24};
    x0 += k0; x1 += k1;
    for (int i = 0; i < 4; i++) { x0 += x1; x1 = tf_rotl(x1, R[i]); x1 ^= x0; }
    x0 += k1;  x1 += ks2 + 1u;
    for (int i = 4; i < 8; i++) { x0 += x1; x1 = tf_rotl(x1, R[i]); x1 ^= x0; }
    x0 += ks2; x1 += k0 + 2u;
    for (int i = 0; i < 4; i++) { x0 += x1; x1 = tf_rotl(x1, R[i]); x1 ^= x0; }
    x0 += k0;  x1 += k1 + 3u;
    for (int i = 4; i < 8; i++) { x0 += x1; x1 = tf_rotl(x1, R[i]); x1 ^= x0; }
    x0 += k1;  x1 += ks2 + 4u;
    for (int i = 0; i < 4; i++) { x0 += x1; x1 = tf_rotl(x1, R[i]); x1 ^= x0; }
    x0 += ks2; x1 += k0 + 5u;
    return TF2{x0, x1};
}

// ---------------- runtime threefry2x32 (JAX partitionable) ----------------
__device__ __forceinline__ void threefry2x32(unsigned k0, unsigned k1,
                                             unsigned x0, unsigned x1,
                                             unsigned& y0, unsigned& y1) {
    unsigned ks2 = 0x1BD11BDAu ^ k0 ^ k1;
#define TF_RND(r) { x0 += x1; x1 = (x1 << (r)) | (x1 >> (32 - (r))); x1 ^= x0; }
    x0 += k0; x1 += k1;
    TF_RND(13) TF_RND(15) TF_RND(26) TF_RND(6)
    x0 += k1;  x1 += ks2 + 1u;
    TF_RND(17) TF_RND(29) TF_RND(16) TF_RND(24)
    x0 += ks2; x1 += k0 + 2u;
    TF_RND(13) TF_RND(15) TF_RND(26) TF_RND(6)
    x0 += k0;  x1 += k1 + 3u;
    TF_RND(17) TF_RND(29) TF_RND(16) TF_RND(24)
    x0 += k1;  x1 += ks2 + 4u;
    TF_RND(13) TF_RND(15) TF_RND(26) TF_RND(6)
    x0 += ks2; x1 += k0 + 5u;
#undef TF_RND
    y0 = x0; y1 = x1;
}
__device__ __forceinline__ unsigned tf_bits32(unsigned k0, unsigned k1, unsigned i) {
    unsigned y0, y1;
    threefry2x32(k0, k1, 0u, i, y0, y1);
    return y0 ^ y1;
}

__device__ __forceinline__ float bits_to_normal(unsigned bits) {
    float f = __uint_as_float((bits >> 9) | 0x3f800000u) - 1.0f;
    const float LO = -0.99999994f;
    float u = fmaxf(LO, f * 2.0f + LO);
    float x = u;
    float w = -log1pf(-x * x);
    float p;
    if (w < 5.0f) {
        w -= 2.5f;
        p =              2.81022636e-08f;
        p = fmaf(p, w,   3.43273939e-07f);
        p = fmaf(p, w,  -3.5233877e-06f);
        p = fmaf(p, w,  -4.39150654e-06f);
        p = fmaf(p, w,   0.00021858087f);
        p = fmaf(p, w,  -0.00125372503f);
        p = fmaf(p, w,  -0.00417768164f);
        p = fmaf(p, w,   0.246640727f);
        p = fmaf(p, w,   1.50140941f);
    } else {
        w = sqrtf(w) - 3.0f;
        p =             -0.000200214257f;
        p = fmaf(p, w,   0.000100950558f);
        p = fmaf(p, w,   0.00134934322f);
        p = fmaf(p, w,  -0.00367342844f);
        p = fmaf(p, w,   0.00573950773f);
        p = fmaf(p, w,  -0.0076224613f);
        p = fmaf(p, w,   0.00943887047f);
        p = fmaf(p, w,   1.00167406f);
        p = fmaf(p, w,   2.83297682f);
    }
    return 1.41421356237f * (p * x);
}

// ---------------- split helper ----------------
__device__ __forceinline__ void split_bf16(float v, __nv_bfloat16& hi, __nv_bfloat16& lo) {
    hi = __float2bfloat16(v);
    lo = __float2bfloat16(v - __bfloat162float(hi));
}

// ---------------- merged: warp-parallel ES scan (block 0) + weight split ----------------
__global__ void scan_wsplit_kernel(const float* __restrict__ x,
                                   const float* __restrict__ lvl_coef,
                                   const float* __restrict__ seas_coef,
                                   const float* __restrict__ seas_params,
                                   const float* __restrict__ W1,
                                   const float* __restrict__ W2) {
    if (blockIdx.x > 0) {
        int i = (blockIdx.x - 1) * 256 + threadIdx.x;
        if (i < WIN * WIN) split_bf16(W1[i], g_w1h[i], g_w1l[i]);
        if (i < WIN * OUTSZ) split_bf16(W2[i], g_w2h[i], g_w2l[i]);
        return;
    }
    if (threadIdx.x >= 32) return;
    const int lane = threadIdx.x;
    const unsigned FULL = 0xFFFFFFFFu;
    for (int i = lane; i < SEAS; i += 32) g_wall[i] = expf(seas_params[i]);
    __syncwarp();
    if (lane == 0) g_wall[SEAS] = g_wall[0];
    __syncwarp();

    const float a = 1.0f / (1.0f + expf(-lvl_coef[0]));
    const float g = 1.0f / (1.0f + expf(-seas_coef[0]));
    const float b = 1.0f - a;
    const float omg = 1.0f - g;
    const float b5 = b * b * b * b * b;
    const float bl = __powf(b5, (float)lane);

    float level = x[0] / g_wall[0];
    if (lane == 0) g_levels[0] = level;

    for (int t0 = 1; t0 < T_LEN; t0 += CHUNK) {
        const int base = t0 + lane * LPL;
        float xi[LPL], se[LPL], c[LPL];
#pragma unroll
        for (int j = 0; j < LPL; j++) {
            int t = base + j;
            if (t < T_LEN) {
                xi[j] = x[t];
                se[j] = g_wall[t];
                c[j]  = __fdividef(a * xi[j], se[j]);
            } else { xi[j] = 1.0f; se[j] = 1.0f; c[j] = 0.0f; }
        }
        float s = 0.0f;
#pragma unroll
        for (int j = 0; j < LPL; j++) s = fmaf(b, s, c[j]);
        float S = s;
        float m = b5;
#pragma unroll
        for (int off = 1; off < 32; off <<= 1) {
            float up = __shfl_up_sync(FULL, S, off);
            if (lane >= off) S = fmaf(m, up, S);
            m = m * m;
        }
        float Sprev = __shfl_up_sync(FULL, S, 1);
        if (lane == 0) Sprev = 0.0f;
        float lvl = fmaf(bl, level, Sprev);
#pragma unroll
        for (int j = 0; j < LPL; j++) {
            int t = base + j;
            if (t < T_LEN) {
                lvl = fmaf(b, lvl, c[j]);
                g_levels[t] = lvl;
                float ns = fmaf(omg, se[j], __fdividef(g * xi[j], lvl));
                if (t + SEAS < T_LEN) g_wall[t + SEAS] = ns;
            }
        }
        level = __shfl_sync(FULL, lvl, 31);
        __syncwarp();
    }
}

// ---------------- parallel log precompute ----------------
__global__ void prep_kernel(const float* __restrict__ x) {
    int i = blockIdx.x * blockDim.x + threadIdx.x;
    if (i < T_LEN) {
        g_llev[i] = logf(g_levels[i]);
        g_c[i]    = logf(x[i]) - logf(g_wall[i]);
    }
}

// ---------------- level variation loss ----------------
__global__ void loss_kernel(float* __restrict__ d_out) {
    __shared__ double sh[256];
    double acc = 0.0;
    for (int i = threadIdx.x; i < T_LEN - 2; i += 256) {
        float d2 = (g_llev[i + 2] - g_llev[i + 1]) - (g_llev[i + 1] - g_llev[i]);
        acc += (double)d2 * (double)d2;
    }
    sh[threadIdx.x] = acc;
    __syncthreads();
    for (int s = 128; s > 0; s >>= 1) {
        if (threadIdx.x < s) sh[threadIdx.x] += sh[threadIdx.x + s];
        __syncthreads();
    }
    if (threadIdx.x == 0)
        d_out[2 * (size_t)N_ROWS * OUTSZ] = (float)(sh[0] / (double)(T_LEN - 2) * (double)LVP_F);
}

// ---------------- inputs matrix -> bf16 hi/lo, incl. zero tail to M_PAD ----------------
__global__ void gen_inputs_kernel() {
    constexpr TF2 K1 = tf2x32_const(0u, 1u, 0u, 0u);
    const unsigned M = (unsigned)N_ROWS * WIN;
    const unsigned MP = (unsigned)M_PAD * WIN;
    unsigned t = blockIdx.x * blockDim.x + threadIdx.x;
    unsigned i0 = 4u * t;
    if (i0 >= MP) return;
    if (i0 >= M) {
        *reinterpret_cast<uint2*>(&g_a_hi[i0]) = make_uint2(0, 0);
        *reinterpret_cast<uint2*>(&g_a_lo[i0]) = make_uint2(0, 0);
        return;
    }
    __nv_bfloat16 hi[4], lo[4];
#pragma unroll
    for (int j = 0; j < 4; j++) {
        unsigned i = i0 + j;
        unsigned n = i / WIN, w = i - n * WIN;
        float z = bits_to_normal(tf_bits32(K1.y0, K1.y1, i));
        float v = g_c[n + w] - g_llev[n + WIN] + STD_NOISE * z;
        split_bf16(v, hi[j], lo[j]);
    }
    *reinterpret_cast<__nv_bfloat162*>(&g_a_hi[i0])     = __nv_bfloat162{hi[0], hi[1]};
    *reinterpret_cast<__nv_bfloat162*>(&g_a_hi[i0 + 2]) = __nv_bfloat162{hi[2], hi[3]};
    *reinterpret_cast<__nv_bfloat162*>(&g_a_lo[i0])     = __nv_bfloat162{lo[0], lo[1]};
    *reinterpret_cast<__nv_bfloat162*>(&g_a_lo[i0 + 2]) = __nv_bfloat162{lo[2], lo[3]};
}

// ---------------- labels directly into d_out ----------------
__global__ void gen_labels_kernel(float* __restrict__ d_out) {
    constexpr TF2 K2 = tf2x32_const(0u, 1u, 0u, 1u);
    const unsigned M = (unsigned)N_ROWS * OUTSZ;
    unsigned t = blockIdx.x * blockDim.x + threadIdx.x;
    unsigned i0 = 4u * t;
    if (i0 >= M) return;
    float* labels = d_out + (size_t)N_ROWS * OUTSZ;
    float v[4];
#pragma unroll
    for (int j = 0; j < 4; j++) {
        unsigned i = i0 + j;
        unsigned n = i / OUTSZ, o = i - n * OUTSZ;
        float z = bits_to_normal(tf_bits32(K2.y0, K2.y1, i));
        v[j] = g_c[n + WIN + o] - g_llev[n + WIN] + STD_NOISE * z;
    }
    *reinterpret_cast<float4*>(&labels[i0]) = make_float4(v[0], v[1], v[2], v[3]);
}

// ---------------- mma / cp.async helpers ----------------
__device__ __forceinline__ unsigned sm_u32(const void* p) {
    return (unsigned)__cvta_generic_to_shared(p);
}
__device__ __forceinline__ void ldsm_x4(unsigned* d, unsigned addr) {
    asm volatile("ldmatrix.sync.aligned.m8n8.x4.shared.b16 {%0,%1,%2,%3}, [%4];"
                 : "=r"(d[0]), "=r"(d[1]), "=r"(d[2]), "=r"(d[3]) : "r"(addr));
}
__device__ __forceinline__ void ldsm_x4t(unsigned* d, unsigned addr) {
    asm volatile("ldmatrix.sync.aligned.m8n8.x4.trans.shared.b16 {%0,%1,%2,%3}, [%4];"
                 : "=r"(d[0]), "=r"(d[1]), "=r"(d[2]), "=r"(d[3]) : "r"(addr));
}
__device__ __forceinline__ void mma16816(float* c, const unsigned* a, unsigned b0, unsigned b1) {
    asm volatile("mma.sync.aligned.m16n8k16.row.col.f32.bf16.bf16.f32 "
                 "{%0,%1,%2,%3}, {%4,%5,%6,%7}, {%8,%9}, {%0,%1,%2,%3};"
                 : "+f"(c[0]), "+f"(c[1]), "+f"(c[2]), "+f"(c[3])
                 : "r"(a[0]), "r"(a[1]), "r"(a[2]), "r"(a[3]), "r"(b0), "r"(b1));
}
__device__ __forceinline__ void cp16(void* s, const void* g) {
    asm volatile("cp.async.cg.shared.global [%0], [%1], 16;"
                 :: "r"(sm_u32(s)), "l"(g));
}
__device__ __forceinline__ void cp16_pred(void* s, const void* g, bool ok) {
    int sz = ok ? 16 : 0;
    asm volatile("cp.async.cg.shared.global [%0], [%1], 16, %2;"
                 :: "r"(sm_u32(s)), "l"(g), "r"(sz));
}
__device__ __forceinline__ void cp_commit() {
    asm volatile("cp.async.commit_group;");
}
template<int N>
__device__ __forceinline__ void cp_wait() {
    asm volatile("cp.async.wait_group %0;" :: "n"(N));
}

// ---------------- GEMM1: hidden = tanh(A@W1 + b1), 3-term bf16, 2-stage cp.async ----
// BM=128, BN=128 (N=336 masked), BK=48. 8 warps as 2m x 4n, warp tile 64x32.
#define G1_AST 72
#define G1_BST 136
__global__ void __launch_bounds__(256, 1)
gemm1_kernel(const float* __restrict__ bias) {
    extern __shared__ char smem[];
    const int tid = threadIdx.x;
    const int wid = tid >> 5, lane = tid & 31;
    const int wm = wid >> 2, wn = wid & 3;
    const int row0 = blockIdx.x * 128;
    const int col0 = blockIdx.y * 128;
    const int lrow = lane & 15, lcol = (lane >> 4) << 3;

    auto sAh = [&](int s) { return (__nv_bfloat16*)(smem + s * G1_STAGE); };
    auto sAl = [&](int s) { return (__nv_bfloat16*)(smem + s * G1_STAGE + 18432); };
    auto sBh = [&](int s) { return (__nv_bfloat16*)(smem + s * G1_STAGE + 36864); };
    auto sBl = [&](int s) { return (__nv_bfloat16*)(smem + s * G1_STAGE + 49920); };

    auto issue = [&](int k0_idx, int s) {
        const int k0 = k0_idx * 48;
        __nv_bfloat16 *ah = sAh(s), *al = sAl(s), *bh = sBh(s), *bl = sBl(s);
        for (int idx = tid; idx < 128 * 6; idx += 256) {
            int r = idx / 6, cb = (idx % 6) * 8;
            size_t go = (size_t)(row0 + r) * WIN + k0 + cb;
            cp16(&ah[r * G1_AST + cb], &g_a_hi[go]);
            cp16(&al[r * G1_AST + cb], &g_a_lo[go]);
        }
        for (int idx = tid; idx < 48 * 16; idx += 256) {
            int r = idx / 16, cb = (idx % 16) * 8;
            int gn = col0 + cb;
            bool ok = gn < WIN;
            size_t go = ok ? (size_t)(k0 + r) * WIN + gn : 0;
            cp16_pred(&bh[r * G1_BST + cb], &g_w1h[go], ok);
            cp16_pred(&bl[r * G1_BST + cb], &g_w1l[go], ok);
        }
    };

    float acc[4][4][4];
#pragma unroll
    for (int i = 0; i < 4; i++)
#pragma unroll
        for (int j = 0; j < 4; j++)
#pragma unroll
            for (int k = 0; k < 4; k++) acc[i][j][k] = 0.0f;

    issue(0, 0);
    cp_commit();

    for (int it = 0; it < 7; it++) {
        const int s = it & 1;
        if (it < 6) {
            issue(it + 1, s ^ 1);
            cp_commit();
            cp_wait<1>();
        } else {
            cp_wait<0>();
        }
        __syncthreads();

        __nv_bfloat16 *ah_s = sAh(s), *al_s = sAl(s), *bh_s = sBh(s), *bl_s = sBl(s);
#pragma unroll
        for (int ks = 0; ks < 3; ks++) {
            unsigned bh[2][4], bl[2][4];
#pragma unroll
            for (int nf2 = 0; nf2 < 2; nf2++) {
                unsigned addr = sm_u32(&bh_s[(ks * 16 + lrow) * G1_BST + wn * 32 + nf2 * 16 + lcol]);
                ldsm_x4t(bh[nf2], addr);
                addr = sm_u32(&bl_s[(ks * 16 + lrow) * G1_BST + wn * 32 + nf2 * 16 + lcol]);
                ldsm_x4t(bl[nf2], addr);
            }
#pragma unroll
            for (int mf = 0; mf < 4; mf++) {
                unsigned ah[4], al[4];
                unsigned addr = sm_u32(&ah_s[(wm * 64 + mf * 16 + lrow) * G1_AST + ks * 16 + lcol]);
                ldsm_x4(ah, addr);
                addr = sm_u32(&al_s[(wm * 64 + mf * 16 + lrow) * G1_AST + ks * 16 + lcol]);
                ldsm_x4(al, addr);
#pragma unroll
                for (int nf2 = 0; nf2 < 2; nf2++) {
#pragma unroll
                    for (int h = 0; h < 2; h++) {
                        int n8 = nf2 * 2 + h;
                        mma16816(acc[mf][n8], ah, bh[nf2][2 * h], bh[nf2][2 * h + 1]);
                        mma16816(acc[mf][n8], al, bh[nf2][2 * h], bh[nf2][2 * h + 1]);
                        mma16816(acc[mf][n8], ah, bl[nf2][2 * h], bl[nf2][2 * h + 1]);
                    }
                }
            }
        }
        __syncthreads();
    }

    const int group = lane >> 2, tig = lane & 3;
#pragma unroll
    for (int mf = 0; mf < 4; mf++) {
#pragma unroll
        for (int n8 = 0; n8 < 4; n8++) {
            int gc = col0 + wn * 32 + n8 * 8 + 2 * tig;
            if (gc >= WIN) continue;
            float b0 = bias[gc], b1 = bias[gc + 1];
            int r0 = row0 + wm * 64 + mf * 16 + group;
#pragma unroll
            for (int half = 0; half < 2; half++) {
                int gr = r0 + half * 8;
                float t0 = tanhf(acc[mf][n8][2 * half] + b0);
                float t1 = tanhf(acc[mf][n8][2 * half + 1] + b1);
                __nv_bfloat16 h0, l0, h1, l1;
                split_bf16(t0, h0, l0);
                split_bf16(t1, h1, l1);
                size_t go = (size_t)gr * WIN + gc;
                *reinterpret_cast<__nv_bfloat162*>(&g_h_hi[go]) = __nv_bfloat162{h0, h1};
                *reinterpret_cast<__nv_bfloat162*>(&g_h_lo[go]) = __nv_bfloat162{l0, l1};
            }
        }
    }
}

// ---------------- GEMM2: out = hidden@W2 + b2, 3-term bf16, 2-stage cp.async ------
// BM=128, BN=48, BK=48. 8 warps as 8m x 1n.
#define G2_BST 72
__global__ void __launch_bounds__(256, 1)
gemm2_kernel(const float* __restrict__ bias, float* __restrict__ out) {
    extern __shared__ char smem[];
    const int tid = threadIdx.x;
    const int wid = tid >> 5, lane = tid & 31;
    const int row0 = blockIdx.x * 128;
    const int lrow = lane & 15, lcol = (lane >> 4) << 3;

    auto sAh = [&](int s) { return (__nv_bfloat16*)(smem + s * G2_STAGE); };
    auto sAl = [&](int s) { return (__nv_bfloat16*)(smem + s * G2_STAGE + 18432); };
    auto sBh = [&](int s) { return (__nv_bfloat16*)(smem + s * G2_STAGE + 36864); };
    auto sBl = [&](int s) { return (__nv_bfloat16*)(smem + s * G2_STAGE + 43776); };

    auto issue = [&](int k0_idx, int s) {
        const int k0 = k0_idx * 48;
        __nv_bfloat16 *ah = sAh(s), *al = sAl(s), *bh = sBh(s), *bl = sBl(s);
        for (int idx = tid; idx < 128 * 6; idx += 256) {
            int r = idx / 6, cb = (idx % 6) * 8;
            size_t go = (size_t)(row0 + r) * WIN + k0 + cb;
            cp16(&ah[r * G1_AST + cb], &g_h_hi[go]);
            cp16(&al[r * G1_AST + cb], &g_h_lo[go]);
        }
        for (int idx = tid; idx < 48 * 6; idx += 256) {
            int r = idx / 6, cb = (idx % 6) * 8;
            size_t go = (size_t)(k0 + r) * OUTSZ + cb;
            cp16(&bh[r * G2_BST + cb], &g_w2h[go]);
            cp16(&bl[r * G2_BST + cb], &g_w2l[go]);
        }
    };

    float acc[6][4];
#pragma unroll
    for (int i = 0; i < 6; i++)
#pragma unroll
        for (int k = 0; k < 4; k++) acc[i][k] = 0.0f;

    issue(0, 0);
    cp_commit();

    for (int it = 0; it < 7; it++) {
        const int s = it & 1;
        if (it < 6) {
            issue(it + 1, s ^ 1);
            cp_commit();
            cp_wait<1>();
        } else {
            cp_wait<0>();
        }
        __syncthreads();

        __nv_bfloat16 *ah_s = sAh(s), *al_s = sAl(s), *bh_s = sBh(s), *bl_s = sBl(s);
#pragma unroll
        for (int ks = 0; ks < 3; ks++) {
            unsigned ah[4], al[4];
            unsigned addr = sm_u32(&ah_s[(wid * 16 + lrow) * G1_AST + ks * 16 + lcol]);
            ldsm_x4(ah, addr);
            addr = sm_u32(&al_s[(wid * 16 + lrow) * G1_AST + ks * 16 + lcol]);
            ldsm_x4(al, addr);
#pragma unroll
            for (int nf2 = 0; nf2 < 3; nf2++) {
                unsigned bh[4], bl[4];
                addr = sm_u32(&bh_s[(ks * 16 + lrow) * G2_BST + nf2 * 16 + lcol]);
                ldsm_x4t(bh, addr);
                addr = sm_u32(&bl_s[(ks * 16 + lrow) * G2_BST + nf2 * 16 + lcol]);
                ldsm_x4t(bl, addr);
#pragma unroll
                for (int h = 0; h < 2; h++) {
                    int n8 = nf2 * 2 + h;
                    mma16816(acc[n8], ah, bh[2 * h], bh[2 * h + 1]);
                    mma16816(acc[n8], al, bh[2 * h], bh[2 * h + 1]);
                    mma16816(acc[n8], ah, bl[2 * h], bl[2 * h + 1]);
                }
            }
        }
        __syncthreads();
    }

    const int group = lane >> 2, tig = lane & 3;
#pragma unroll
    for (int n8 = 0; n8 < 6; n8++) {
        int gc = n8 * 8 + 2 * tig;
        float b0 = bias[gc], b1 = bias[gc + 1];
        int r0 = row0 + wid * 16 + group;
#pragma unroll
        for (int half = 0; half < 2; half++) {
            int gr = r0 + half * 8;
            if (gr < N_ROWS) {
                float2 v = make_float2(acc[n8][2 * half] + b0, acc[n8][2 * half + 1] + b1);
                *reinterpret_cast<float2*>(&out[(size_t)gr * OUTSZ + gc]) = v;
            }
        }
    }
}

// ---------------- launch ----------------
extern "C" void kernel_launch(void* const* d_in, const int* in_sizes, int n_in,
                              void* d_out, int out_size) {
    const float* x           = (const float*)d_in[0];
    const float* lvl_coef    = (const float*)d_in[1];
    const float* seas_coef   = (const float*)d_in[2];
    const float* seas_params = (const float*)d_in[3];
    const float* W_tanh      = (const float*)d_in[4];
    const float* b_tanh      = (const float*)d_in[5];
    const float* W_out       = (const float*)d_in[6];
    const float* b_out       = (const float*)d_in[7];
    float* out = (float*)d_out;

    cudaFuncSetAttribute(gemm1_kernel, cudaFuncAttributeMaxDynamicSharedMemorySize, G1_SMEM);
    cudaFuncSetAttribute(gemm2_kernel, cudaFuncAttributeMaxDynamicSharedMemorySize, G2_SMEM);

    // order chosen so gemm1 is launch index 3 (profiled by the harness ncu capture)
    scan_wsplit_kernel<<<1 + (WIN * WIN + 255) / 256, 256>>>(
        x, lvl_coef, seas_coef, seas_params, W_tanh, W_out);
    prep_kernel<<<(T_LEN + 255) / 256, 256>>>(x);
    {
        unsigned P = ((unsigned)M_PAD * WIN) / 4u;
        gen_inputs_kernel<<<(P + 255) / 256, 256>>>();
    }
    {
        dim3 grid(M_PAD / 128, 3);
        gemm1_kernel<<<grid, 256, G1_SMEM>>>(b_tanh);
    }
    {
        unsigned P = ((unsigned)N_ROWS * OUTSZ) / 4u;
        gen_labels_kernel<<<(P + 255) / 256, 256>>>(out);
    }
    loss_kernel<<<1, 256>>>(out);
    {
        dim3 grid(M_PAD / 128);
        gemm2_kernel<<<grid, 256, G2_SMEM>>>(b_out, out);
    }
    (void)in_sizes; (void)n_in; (void)out_size;
}

// round 10
// speedup vs baseline: 2.8615x; 1.3542x over previous
#include <cuda_runtime.h>
#include <cuda_bf16.h>
#include <math.h>

#define T_LEN 100000
#define WIN   336
#define OUTSZ 48
#define SEAS  168
#define N_ROWS (T_LEN - WIN - OUTSZ + 1)   // 99617
#define M_PAD  99712                        // 779 * 128
#define STD_NOISE 0.001f
#define LVP_F 50.0f
#define CHUNK 160
#define LPL 5

#define G1_STAGE 62976
#define G1_SMEM  (2 * G1_STAGE)
#define G2_STAGE 50688
#define G2_SMEM  (2 * G2_STAGE)

// ---------------- device scratch ----------------
__device__ float g_levels[T_LEN];
__device__ float g_wall[T_LEN];
__device__ float g_llev[T_LEN];
__device__ float g_c[T_LEN];
__device__ __nv_bfloat16 g_a_hi[(size_t)M_PAD * WIN];
__device__ __nv_bfloat16 g_a_lo[(size_t)M_PAD * WIN];
__device__ __nv_bfloat16 g_h_hi[(size_t)M_PAD * WIN];
__device__ __nv_bfloat16 g_h_lo[(size_t)M_PAD * WIN];
__device__ __nv_bfloat16 g_w1h[WIN * WIN], g_w1l[WIN * WIN];
__device__ __nv_bfloat16 g_w2h[WIN * OUTSZ], g_w2l[WIN * OUTSZ];

// ---------------- compile-time threefry ----------------
struct TF2 { unsigned y0, y1; };
__host__ __device__ constexpr unsigned tf_rotl(unsigned x, int r) {
    return (x << r) | (x >> (32 - r));
}
__host__ __device__ constexpr TF2 tf2x32_const(unsigned k0, unsigned k1,
                                               unsigned x0, unsigned x1) {
    unsigned ks2 = 0x1BD11BDAu ^ k0 ^ k1;
    const int R[8] = {13, 15, 26, 6, 17, 29, 16, 24};
    x0 += k0; x1 += k1;
    for (int i = 0; i < 4; i++) { x0 += x1; x1 = tf_rotl(x1, R[i]); x1 ^= x0; }
    x0 += k1;  x1 += ks2 + 1u;
    for (int i = 4; i < 8; i++) { x0 += x1; x1 = tf_rotl(x1, R[i]); x1 ^= x0; }
    x0 += ks2; x1 += k0 + 2u;
    for (int i = 0; i < 4; i++) { x0 += x1; x1 = tf_rotl(x1, R[i]); x1 ^= x0; }
    x0 += k0;  x1 += k1 + 3u;
    for (int i = 4; i < 8; i++) { x0 += x1; x1 = tf_rotl(x1, R[i]); x1 ^= x0; }
    x0 += k1;  x1 += ks2 + 4u;
    for (int i = 0; i < 4; i++) { x0 += x1; x1 = tf_rotl(x1, R[i]); x1 ^= x0; }
    x0 += ks2; x1 += k0 + 5u;
    return TF2{x0, x1};
}

// ---------------- runtime threefry2x32 (JAX partitionable) ----------------
__device__ __forceinline__ void threefry2x32(unsigned k0, unsigned k1,
                                             unsigned x0, unsigned x1,
                                             unsigned& y0, unsigned& y1) {
    unsigned ks2 = 0x1BD11BDAu ^ k0 ^ k1;
#define TF_RND(r) { x0 += x1; x1 = (x1 << (r)) | (x1 >> (32 - (r))); x1 ^= x0; }
    x0 += k0; x1 += k1;
    TF_RND(13) TF_RND(15) TF_RND(26) TF_RND(6)
    x0 += k1;  x1 += ks2 + 1u;
    TF_RND(17) TF_RND(29) TF_RND(16) TF_RND(24)
    x0 += ks2; x1 += k0 + 2u;
    TF_RND(13) TF_RND(15) TF_RND(26) TF_RND(6)
    x0 += k0;  x1 += k1 + 3u;
    TF_RND(17) TF_RND(29) TF_RND(16) TF_RND(24)
    x0 += k1;  x1 += ks2 + 4u;
    TF_RND(13) TF_RND(15) TF_RND(26) TF_RND(6)
    x0 += ks2; x1 += k0 + 5u;
#undef TF_RND
    y0 = x0; y1 = x1;
}
__device__ __forceinline__ unsigned tf_bits32(unsigned k0, unsigned k1, unsigned i) {
    unsigned y0, y1;
    threefry2x32(k0, k1, 0u, i, y0, y1);
    return y0 ^ y1;
}

__device__ __forceinline__ float bits_to_normal(unsigned bits) {
    float f = __uint_as_float((bits >> 9) | 0x3f800000u) - 1.0f;
    const float LO = -0.99999994f;
    float u = fmaxf(LO, f * 2.0f + LO);
    float x = u;
    float w = -log1pf(-x * x);
    float p;
    if (w < 5.0f) {
        w -= 2.5f;
        p =              2.81022636e-08f;
        p = fmaf(p, w,   3.43273939e-07f);
        p = fmaf(p, w,  -3.5233877e-06f);
        p = fmaf(p, w,  -4.39150654e-06f);
        p = fmaf(p, w,   0.00021858087f);
        p = fmaf(p, w,  -0.00125372503f);
        p = fmaf(p, w,  -0.00417768164f);
        p = fmaf(p, w,   0.246640727f);
        p = fmaf(p, w,   1.50140941f);
    } else {
        w = sqrtf(w) - 3.0f;
        p =             -0.000200214257f;
        p = fmaf(p, w,   0.000100950558f);
        p = fmaf(p, w,   0.00134934322f);
        p = fmaf(p, w,  -0.00367342844f);
        p = fmaf(p, w,   0.00573950773f);
        p = fmaf(p, w,  -0.0076224613f);
        p = fmaf(p, w,   0.00943887047f);
        p = fmaf(p, w,   1.00167406f);
        p = fmaf(p, w,   2.83297682f);
    }
    return 1.41421356237f * (p * x);
}

// ---------------- split helper ----------------
__device__ __forceinline__ void split_bf16(float v, __nv_bfloat16& hi, __nv_bfloat16& lo) {
    hi = __float2bfloat16(v);
    lo = __float2bfloat16(v - __bfloat162float(hi));
}

// ---------------- scan (smem season ring + x prefetch) + weight split ----------------
__global__ void scan_wsplit_kernel(const float* __restrict__ x,
                                   const float* __restrict__ lvl_coef,
                                   const float* __restrict__ seas_coef,
                                   const float* __restrict__ seas_params,
                                   const float* __restrict__ W1,
                                   const float* __restrict__ W2) {
    __shared__ float ring[512];            // season ring, index t & 511 (live span 168+CHUNK < 512)
    if (blockIdx.x > 0) {
        int i = (blockIdx.x - 1) * 256 + threadIdx.x;
        if (i < WIN * WIN) split_bf16(W1[i], g_w1h[i], g_w1l[i]);
        if (i < WIN * OUTSZ) split_bf16(W2[i], g_w2h[i], g_w2l[i]);
        return;
    }
    if (threadIdx.x >= 32) return;
    const int lane = threadIdx.x;
    const unsigned FULL = 0xFFFFFFFFu;
    for (int i = lane; i < SEAS; i += 32) {
        float w = expf(seas_params[i]);
        ring[i] = w;
        g_wall[i] = w;
    }
    __syncwarp();
    if (lane == 0) { ring[SEAS] = ring[0]; g_wall[SEAS] = ring[0]; }
    __syncwarp();

    const float a = 1.0f / (1.0f + expf(-lvl_coef[0]));
    const float g = 1.0f / (1.0f + expf(-seas_coef[0]));
    const float b = 1.0f - a;
    const float omg = 1.0f - g;
    const float b5 = b * b * b * b * b;
    const float bl = __powf(b5, (float)lane);

    float level = x[0] / ring[0];
    if (lane == 0) g_levels[0] = level;

    // prefetch x for first chunk
    float xn[LPL];
    {
        const int base = 1 + lane * LPL;
#pragma unroll
        for (int j = 0; j < LPL; j++)
            xn[j] = (base + j < T_LEN) ? __ldg(&x[base + j]) : 1.0f;
    }

    for (int t0 = 1; t0 < T_LEN; t0 += CHUNK) {
        const int base = t0 + lane * LPL;
        float xi[LPL];
#pragma unroll
        for (int j = 0; j < LPL; j++) xi[j] = xn[j];
        // prefetch next chunk's x (independent of the serial chain; hides DRAM latency)
        {
            const int nbase = t0 + CHUNK + lane * LPL;
#pragma unroll
            for (int j = 0; j < LPL; j++)
                xn[j] = (nbase + j < T_LEN) ? __ldg(&x[nbase + j]) : 1.0f;
        }
        float se[LPL], c[LPL];
#pragma unroll
        for (int j = 0; j < LPL; j++) {
            int t = base + j;
            if (t < T_LEN) {
                se[j] = ring[t & 511];
                c[j]  = __fdividef(a * xi[j], se[j]);
            } else { se[j] = 1.0f; c[j] = 0.0f; }
        }
        float s = 0.0f;
#pragma unroll
        for (int j = 0; j < LPL; j++) s = fmaf(b, s, c[j]);
        float S = s;
        float m = b5;
#pragma unroll
        for (int off = 1; off < 32; off <<= 1) {
            float up = __shfl_up_sync(FULL, S, off);
            if (lane >= off) S = fmaf(m, up, S);
            m = m * m;
        }
        float Sprev = __shfl_up_sync(FULL, S, 1);
        if (lane == 0) Sprev = 0.0f;
        float lvl = fmaf(bl, level, Sprev);
#pragma unroll
        for (int j = 0; j < LPL; j++) {
            int t = base + j;
            if (t < T_LEN) {
                lvl = fmaf(b, lvl, c[j]);
                g_levels[t] = lvl;
                float ns = fmaf(omg, se[j], __fdividef(g * xi[j], lvl));
                ring[(t + SEAS) & 511] = ns;
                if (t + SEAS < T_LEN) g_wall[t + SEAS] = ns;
            }
        }
        level = __shfl_sync(FULL, lvl, 31);
        __syncwarp();
    }
}

// ---------------- parallel log precompute ----------------
__global__ void prep_kernel(const float* __restrict__ x) {
    int i = blockIdx.x * blockDim.x + threadIdx.x;
    if (i < T_LEN) {
        g_llev[i] = logf(g_levels[i]);
        g_c[i]    = logf(x[i]) - logf(g_wall[i]);
    }
}

// ---------------- level variation loss ----------------
__global__ void loss_kernel(float* __restrict__ d_out) {
    __shared__ double sh[256];
    double acc = 0.0;
    for (int i = threadIdx.x; i < T_LEN - 2; i += 256) {
        float d2 = (g_llev[i + 2] - g_llev[i + 1]) - (g_llev[i + 1] - g_llev[i]);
        acc += (double)d2 * (double)d2;
    }
    sh[threadIdx.x] = acc;
    __syncthreads();
    for (int s = 128; s > 0; s >>= 1) {
        if (threadIdx.x < s) sh[threadIdx.x] += sh[threadIdx.x + s];
        __syncthreads();
    }
    if (threadIdx.x == 0)
        d_out[2 * (size_t)N_ROWS * OUTSZ] = (float)(sh[0] / (double)(T_LEN - 2) * (double)LVP_F);
}

// ---------------- inputs matrix -> bf16 hi/lo, incl. zero tail to M_PAD ----------------
__global__ void gen_inputs_kernel() {
    constexpr TF2 K1 = tf2x32_const(0u, 1u, 0u, 0u);
    const unsigned M = (unsigned)N_ROWS * WIN;
    const unsigned MP = (unsigned)M_PAD * WIN;
    unsigned t = blockIdx.x * blockDim.x + threadIdx.x;
    unsigned i0 = 4u * t;
    if (i0 >= MP) return;
    if (i0 >= M) {
        *reinterpret_cast<uint2*>(&g_a_hi[i0]) = make_uint2(0, 0);
        *reinterpret_cast<uint2*>(&g_a_lo[i0]) = make_uint2(0, 0);
        return;
    }
    __nv_bfloat16 hi[4], lo[4];
#pragma unroll
    for (int j = 0; j < 4; j++) {
        unsigned i = i0 + j;
        unsigned n = i / WIN, w = i - n * WIN;
        float z = bits_to_normal(tf_bits32(K1.y0, K1.y1, i));
        float v = g_c[n + w] - g_llev[n + WIN] + STD_NOISE * z;
        split_bf16(v, hi[j], lo[j]);
    }
    *reinterpret_cast<__nv_bfloat162*>(&g_a_hi[i0])     = __nv_bfloat162{hi[0], hi[1]};
    *reinterpret_cast<__nv_bfloat162*>(&g_a_hi[i0 + 2]) = __nv_bfloat162{hi[2], hi[3]};
    *reinterpret_cast<__nv_bfloat162*>(&g_a_lo[i0])     = __nv_bfloat162{lo[0], lo[1]};
    *reinterpret_cast<__nv_bfloat162*>(&g_a_lo[i0 + 2]) = __nv_bfloat162{lo[2], lo[3]};
}

// ---------------- labels directly into d_out ----------------
__global__ void gen_labels_kernel(float* __restrict__ d_out) {
    constexpr TF2 K2 = tf2x32_const(0u, 1u, 0u, 1u);
    const unsigned M = (unsigned)N_ROWS * OUTSZ;
    unsigned t = blockIdx.x * blockDim.x + threadIdx.x;
    unsigned i0 = 4u * t;
    if (i0 >= M) return;
    float* labels = d_out + (size_t)N_ROWS * OUTSZ;
    float v[4];
#pragma unroll
    for (int j = 0; j < 4; j++) {
        unsigned i = i0 + j;
        unsigned n = i / OUTSZ, o = i - n * OUTSZ;
        float z = bits_to_normal(tf_bits32(K2.y0, K2.y1, i));
        v[j] = g_c[n + WIN + o] - g_llev[n + WIN] + STD_NOISE * z;
    }
    *reinterpret_cast<float4*>(&labels[i0]) = make_float4(v[0], v[1], v[2], v[3]);
}

// ---------------- mma / cp.async helpers ----------------
__device__ __forceinline__ unsigned sm_u32(const void* p) {
    return (unsigned)__cvta_generic_to_shared(p);
}
__device__ __forceinline__ void ldsm_x4(unsigned* d, unsigned addr) {
    asm volatile("ldmatrix.sync.aligned.m8n8.x4.shared.b16 {%0,%1,%2,%3}, [%4];"
                 : "=r"(d[0]), "=r"(d[1]), "=r"(d[2]), "=r"(d[3]) : "r"(addr));
}
__device__ __forceinline__ void ldsm_x4t(unsigned* d, unsigned addr) {
    asm volatile("ldmatrix.sync.aligned.m8n8.x4.trans.shared.b16 {%0,%1,%2,%3}, [%4];"
                 : "=r"(d[0]), "=r"(d[1]), "=r"(d[2]), "=r"(d[3]) : "r"(addr));
}
__device__ __forceinline__ void mma16816(float* c, const unsigned* a, unsigned b0, unsigned b1) {
    asm volatile("mma.sync.aligned.m16n8k16.row.col.f32.bf16.bf16.f32 "
                 "{%0,%1,%2,%3}, {%4,%5,%6,%7}, {%8,%9}, {%0,%1,%2,%3};"
                 : "+f"(c[0]), "+f"(c[1]), "+f"(c[2]), "+f"(c[3])
                 : "r"(a[0]), "r"(a[1]), "r"(a[2]), "r"(a[3]), "r"(b0), "r"(b1));
}
__device__ __forceinline__ void cp16(void* s, const void* g) {
    asm volatile("cp.async.cg.shared.global [%0], [%1], 16;"
                 :: "r"(sm_u32(s)), "l"(g));
}
__device__ __forceinline__ void cp16_pred(void* s, const void* g, bool ok) {
    int sz = ok ? 16 : 0;
    asm volatile("cp.async.cg.shared.global [%0], [%1], 16, %2;"
                 :: "r"(sm_u32(s)), "l"(g), "r"(sz));
}
__device__ __forceinline__ void cp_commit() {
    asm volatile("cp.async.commit_group;");
}
template<int N>
__device__ __forceinline__ void cp_wait() {
    asm volatile("cp.async.wait_group %0;" :: "n"(N));
}

// ---------------- GEMM1: hidden = tanh(A@W1 + b1), 3-term bf16, 2-stage cp.async ----
#define G1_AST 72
#define G1_BST 136
__global__ void __launch_bounds__(256, 1)
gemm1_kernel(const float* __restrict__ bias) {
    extern __shared__ char smem[];
    const int tid = threadIdx.x;
    const int wid = tid >> 5, lane = tid & 31;
    const int wm = wid >> 2, wn = wid & 3;
    const int row0 = blockIdx.x * 128;
    const int col0 = blockIdx.y * 128;
    const int lrow = lane & 15, lcol = (lane >> 4) << 3;

    auto sAh = [&](int s) { return (__nv_bfloat16*)(smem + s * G1_STAGE); };
    auto sAl = [&](int s) { return (__nv_bfloat16*)(smem + s * G1_STAGE + 18432); };
    auto sBh = [&](int s) { return (__nv_bfloat16*)(smem + s * G1_STAGE + 36864); };
    auto sBl = [&](int s) { return (__nv_bfloat16*)(smem + s * G1_STAGE + 49920); };

    auto issue = [&](int k0_idx, int s) {
        const int k0 = k0_idx * 48;
        __nv_bfloat16 *ah = sAh(s), *al = sAl(s), *bh = sBh(s), *bl = sBl(s);
        for (int idx = tid; idx < 128 * 6; idx += 256) {
            int r = idx / 6, cb = (idx % 6) * 8;
            size_t go = (size_t)(row0 + r) * WIN + k0 + cb;
            cp16(&ah[r * G1_AST + cb], &g_a_hi[go]);
            cp16(&al[r * G1_AST + cb], &g_a_lo[go]);
        }
        for (int idx = tid; idx < 48 * 16; idx += 256) {
            int r = idx / 16, cb = (idx % 16) * 8;
            int gn = col0 + cb;
            bool ok = gn < WIN;
            size_t go = ok ? (size_t)(k0 + r) * WIN + gn : 0;
            cp16_pred(&bh[r * G1_BST + cb], &g_w1h[go], ok);
            cp16_pred(&bl[r * G1_BST + cb], &g_w1l[go], ok);
        }
    };

    float acc[4][4][4];
#pragma unroll
    for (int i = 0; i < 4; i++)
#pragma unroll
        for (int j = 0; j < 4; j++)
#pragma unroll
            for (int k = 0; k < 4; k++) acc[i][j][k] = 0.0f;

    issue(0, 0);
    cp_commit();

    for (int it = 0; it < 7; it++) {
        const int s = it & 1;
        if (it < 6) {
            issue(it + 1, s ^ 1);
            cp_commit();
            cp_wait<1>();
        } else {
            cp_wait<0>();
        }
        __syncthreads();

        __nv_bfloat16 *ah_s = sAh(s), *al_s = sAl(s), *bh_s = sBh(s), *bl_s = sBl(s);
#pragma unroll
        for (int ks = 0; ks < 3; ks++) {
            unsigned bh[2][4], bl[2][4];
#pragma unroll
            for (int nf2 = 0; nf2 < 2; nf2++) {
                unsigned addr = sm_u32(&bh_s[(ks * 16 + lrow) * G1_BST + wn * 32 + nf2 * 16 + lcol]);
                ldsm_x4t(bh[nf2], addr);
                addr = sm_u32(&bl_s[(ks * 16 + lrow) * G1_BST + wn * 32 + nf2 * 16 + lcol]);
                ldsm_x4t(bl[nf2], addr);
            }
#pragma unroll
            for (int mf = 0; mf < 4; mf++) {
                unsigned ah[4], al[4];
                unsigned addr = sm_u32(&ah_s[(wm * 64 + mf * 16 + lrow) * G1_AST + ks * 16 + lcol]);
                ldsm_x4(ah, addr);
                addr = sm_u32(&al_s[(wm * 64 + mf * 16 + lrow) * G1_AST + ks * 16 + lcol]);
                ldsm_x4(al, addr);
#pragma unroll
                for (int nf2 = 0; nf2 < 2; nf2++) {
#pragma unroll
                    for (int h = 0; h < 2; h++) {
                        int n8 = nf2 * 2 + h;
                        mma16816(acc[mf][n8], ah, bh[nf2][2 * h], bh[nf2][2 * h + 1]);
                        mma16816(acc[mf][n8], al, bh[nf2][2 * h], bh[nf2][2 * h + 1]);
                        mma16816(acc[mf][n8], ah, bl[nf2][2 * h], bl[nf2][2 * h + 1]);
                    }
                }
            }
        }
        __syncthreads();
    }

    const int group = lane >> 2, tig = lane & 3;
#pragma unroll
    for (int mf = 0; mf < 4; mf++) {
#pragma unroll
        for (int n8 = 0; n8 < 4; n8++) {
            int gc = col0 + wn * 32 + n8 * 8 + 2 * tig;
            if (gc >= WIN) continue;
            float b0 = bias[gc], b1 = bias[gc + 1];
            int r0 = row0 + wm * 64 + mf * 16 + group;
#pragma unroll
            for (int half = 0; half < 2; half++) {
                int gr = r0 + half * 8;
                float t0 = tanhf(acc[mf][n8][2 * half] + b0);
                float t1 = tanhf(acc[mf][n8][2 * half + 1] + b1);
                __nv_bfloat16 h0, l0, h1, l1;
                split_bf16(t0, h0, l0);
                split_bf16(t1, h1, l1);
                size_t go = (size_t)gr * WIN + gc;
                *reinterpret_cast<__nv_bfloat162*>(&g_h_hi[go]) = __nv_bfloat162{h0, h1};
                *reinterpret_cast<__nv_bfloat162*>(&g_h_lo[go]) = __nv_bfloat162{l0, l1};
            }
        }
    }
}

// ---------------- GEMM2: out = hidden@W2 + b2, 3-term bf16, 2-stage cp.async ------
#define G2_BST 72
__global__ void __launch_bounds__(256, 1)
gemm2_kernel(const float* __restrict__ bias, float* __restrict__ out) {
    extern __shared__ char smem[];
    const int tid = threadIdx.x;
    const int wid = tid >> 5, lane = tid & 31;
    const int row0 = blockIdx.x * 128;
    const int lrow = lane & 15, lcol = (lane >> 4) << 3;

    auto sAh = [&](int s) { return (__nv_bfloat16*)(smem + s * G2_STAGE); };
    auto sAl = [&](int s) { return (__nv_bfloat16*)(smem + s * G2_STAGE + 18432); };
    auto sBh = [&](int s) { return (__nv_bfloat16*)(smem + s * G2_STAGE + 36864); };
    auto sBl = [&](int s) { return (__nv_bfloat16*)(smem + s * G2_STAGE + 43776); };

    auto issue = [&](int k0_idx, int s) {
        const int k0 = k0_idx * 48;
        __nv_bfloat16 *ah = sAh(s), *al = sAl(s), *bh = sBh(s), *bl = sBl(s);
        for (int idx = tid; idx < 128 * 6; idx += 256) {
            int r = idx / 6, cb = (idx % 6) * 8;
            size_t go = (size_t)(row0 + r) * WIN + k0 + cb;
            cp16(&ah[r * G1_AST + cb], &g_h_hi[go]);
            cp16(&al[r * G1_AST + cb], &g_h_lo[go]);
        }
        for (int idx = tid; idx < 48 * 6; idx += 256) {
            int r = idx / 6, cb = (idx % 6) * 8;
            size_t go = (size_t)(k0 + r) * OUTSZ + cb;
            cp16(&bh[r * G2_BST + cb], &g_w2h[go]);
            cp16(&bl[r * G2_BST + cb], &g_w2l[go]);
        }
    };

    float acc[6][4];
#pragma unroll
    for (int i = 0; i < 6; i++)
#pragma unroll
        for (int k = 0; k < 4; k++) acc[i][k] = 0.0f;

    issue(0, 0);
    cp_commit();

    for (int it = 0; it < 7; it++) {
        const int s = it & 1;
        if (it < 6) {
            issue(it + 1, s ^ 1);
            cp_commit();
            cp_wait<1>();
        } else {
            cp_wait<0>();
        }
        __syncthreads();

        __nv_bfloat16 *ah_s = sAh(s), *al_s = sAl(s), *bh_s = sBh(s), *bl_s = sBl(s);
#pragma unroll
        for (int ks = 0; ks < 3; ks++) {
            unsigned ah[4], al[4];
            unsigned addr = sm_u32(&ah_s[(wid * 16 + lrow) * G1_AST + ks * 16 + lcol]);
            ldsm_x4(ah, addr);
            addr = sm_u32(&al_s[(wid * 16 + lrow) * G1_AST + ks * 16 + lcol]);
            ldsm_x4(al, addr);
#pragma unroll
            for (int nf2 = 0; nf2 < 3; nf2++) {
                unsigned bh[4], bl[4];
                addr = sm_u32(&bh_s[(ks * 16 + lrow) * G2_BST + nf2 * 16 + lcol]);
                ldsm_x4t(bh, addr);
                addr = sm_u32(&bl_s[(ks * 16 + lrow) * G2_BST + nf2 * 16 + lcol]);
                ldsm_x4t(bl, addr);
#pragma unroll
                for (int h = 0; h < 2; h++) {
                    int n8 = nf2 * 2 + h;
                    mma16816(acc[n8], ah, bh[2 * h], bh[2 * h + 1]);
                    mma16816(acc[n8], al, bh[2 * h], bh[2 * h + 1]);
                    mma16816(acc[n8], ah, bl[2 * h], bl[2 * h + 1]);
                }
            }
        }
        __syncthreads();
    }

    const int group = lane >> 2, tig = lane & 3;
#pragma unroll
    for (int n8 = 0; n8 < 6; n8++) {
        int gc = n8 * 8 + 2 * tig;
        float b0 = bias[gc], b1 = bias[gc + 1];
        int r0 = row0 + wid * 16 + group;
#pragma unroll
        for (int half = 0; half < 2; half++) {
            int gr = r0 + half * 8;
            if (gr < N_ROWS) {
                float2 v = make_float2(acc[n8][2 * half] + b0, acc[n8][2 * half + 1] + b1);
                *reinterpret_cast<float2*>(&out[(size_t)gr * OUTSZ + gc]) = v;
            }
        }
    }
}

// ---------------- launch ----------------
extern "C" void kernel_launch(void* const* d_in, const int* in_sizes, int n_in,
                              void* d_out, int out_size) {
    const float* x           = (const float*)d_in[0];
    const float* lvl_coef    = (const float*)d_in[1];
    const float* seas_coef   = (const float*)d_in[2];
    const float* seas_params = (const float*)d_in[3];
    const float* W_tanh      = (const float*)d_in[4];
    const float* b_tanh      = (const float*)d_in[5];
    const float* W_out       = (const float*)d_in[6];
    const float* b_out       = (const float*)d_in[7];
    float* out = (float*)d_out;

    cudaFuncSetAttribute(gemm1_kernel, cudaFuncAttributeMaxDynamicSharedMemorySize, G1_SMEM);
    cudaFuncSetAttribute(gemm2_kernel, cudaFuncAttributeMaxDynamicSharedMemorySize, G2_SMEM);

    // gemm1 stays at launch index 3 (profiled by the harness ncu capture)
    scan_wsplit_kernel<<<1 + (WIN * WIN + 255) / 256, 256>>>(
        x, lvl_coef, seas_coef, seas_params, W_tanh, W_out);
    prep_kernel<<<(T_LEN + 255) / 256, 256>>>(x);
    {
        unsigned P = ((unsigned)M_PAD * WIN) / 4u;
        gen_inputs_kernel<<<(P + 255) / 256, 256>>>();
    }
    {
        dim3 grid(M_PAD / 128, 3);
        gemm1_kernel<<<grid, 256, G1_SMEM>>>(b_tanh);
    }
    {
        unsigned P = ((unsigned)N_ROWS * OUTSZ) / 4u;
        gen_labels_kernel<<<(P + 255) / 256, 256>>>(out);
    }
    loss_kernel<<<1, 256>>>(out);
    {
        dim3 grid(M_PAD / 128);
        gemm2_kernel<<<grid, 256, G2_SMEM>>>(b_out, out);
    }
    (void)in_sizes; (void)n_in; (void)out_size;
}

// round 12
// speedup vs baseline: 2.9294x; 1.0237x over previous
#include <cuda_runtime.h>
#include <cuda_bf16.h>
#include <math.h>

#define T_LEN 100000
#define WIN   336
#define OUTSZ 48
#define SEAS  168
#define N_ROWS (T_LEN - WIN - OUTSZ + 1)   // 99617
#define M_PAD  99712                        // 779 * 128
#define STD_NOISE 0.001f
#define LVP_F 50.0f
#define CHUNK 160
#define LPL 5

#define G1_STAGE 62976
#define G1_SMEM  (2 * G1_STAGE)
#define G2_STAGE 50688
#define G2_SMEM  (2 * G2_STAGE)

// ---------------- device scratch ----------------
__device__ float g_levels[T_LEN];
__device__ float g_wall[T_LEN];
__device__ float g_llev[T_LEN];
__device__ float g_c[T_LEN];
__device__ __nv_bfloat16 g_a_hi[(size_t)M_PAD * WIN];
__device__ __nv_bfloat16 g_a_lo[(size_t)M_PAD * WIN];
__device__ __nv_bfloat16 g_h_hi[(size_t)M_PAD * WIN];
__device__ __nv_bfloat16 g_h_lo[(size_t)M_PAD * WIN];
__device__ __nv_bfloat16 g_w1h[WIN * WIN], g_w1l[WIN * WIN];
__device__ __nv_bfloat16 g_w2h[WIN * OUTSZ], g_w2l[WIN * OUTSZ];

// ---------------- compile-time threefry ----------------
struct TF2 { unsigned y0, y1; };
__host__ __device__ constexpr unsigned tf_rotl(unsigned x, int r) {
    return (x << r) | (x >> (32 - r));
}
__host__ __device__ constexpr TF2 tf2x32_const(unsigned k0, unsigned k1,
                                               unsigned x0, unsigned x1) {
    unsigned ks2 = 0x1BD11BDAu ^ k0 ^ k1;
    const int R[8] = {13, 15, 26, 6, 17, 29, 16, 24};
    x0 += k0; x1 += k1;
    for (int i = 0; i < 4; i++) { x0 += x1; x1 = tf_rotl(x1, R[i]); x1 ^= x0; }
    x0 += k1;  x1 += ks2 + 1u;
    for (int i = 4; i < 8; i++) { x0 += x1; x1 = tf_rotl(x1, R[i]); x1 ^= x0; }
    x0 += ks2; x1 += k0 + 2u;
    for (int i = 0; i < 4; i++) { x0 += x1; x1 = tf_rotl(x1, R[i]); x1 ^= x0; }
    x0 += k0;  x1 += k1 + 3u;
    for (int i = 4; i < 8; i++) { x0 += x1; x1 = tf_rotl(x1, R[i]); x1 ^= x0; }
    x0 += k1;  x1 += ks2 + 4u;
    for (int i = 0; i < 4; i++) { x0 += x1; x1 = tf_rotl(x1, R[i]); x1 ^= x0; }
    x0 += ks2; x1 += k0 + 5u;
    return TF2{x0, x1};
}

// ---------------- runtime threefry2x32 (JAX partitionable) ----------------
__device__ __forceinline__ void threefry2x32(unsigned k0, unsigned k1,
                                             unsigned x0, unsigned x1,
                                             unsigned& y0, unsigned& y1) {
    unsigned ks2 = 0x1BD11BDAu ^ k0 ^ k1;
#define TF_RND(r) { x0 += x1; x1 = (x1 << (r)) | (x1 >> (32 - (r))); x1 ^= x0; }
    x0 += k0; x1 += k1;
    TF_RND(13) TF_RND(15) TF_RND(26) TF_RND(6)
    x0 += k1;  x1 += ks2 + 1u;
    TF_RND(17) TF_RND(29) TF_RND(16) TF_RND(24)
    x0 += ks2; x1 += k0 + 2u;
    TF_RND(13) TF_RND(15) TF_RND(26) TF_RND(6)
    x0 += k0;  x1 += k1 + 3u;
    TF_RND(17) TF_RND(29) TF_RND(16) TF_RND(24)
    x0 += k1;  x1 += ks2 + 4u;
    TF_RND(13) TF_RND(15) TF_RND(26) TF_RND(6)
    x0 += ks2; x1 += k0 + 5u;
#undef TF_RND
    y0 = x0; y1 = x1;
}
__device__ __forceinline__ unsigned tf_bits32(unsigned k0, unsigned k1, unsigned i) {
    unsigned y0, y1;
    threefry2x32(k0, k1, 0u, i, y0, y1);
    return y0 ^ y1;
}

__device__ __forceinline__ float bits_to_normal(unsigned bits) {
    float f = __uint_as_float((bits >> 9) | 0x3f800000u) - 1.0f;
    const float LO = -0.99999994f;
    float u = fmaxf(LO, f * 2.0f + LO);
    float x = u;
    // log1p(-x*x) == log(1 - x*x); fmaf gives 1-x*x with one rounding (no cancellation),
    // __logf (MUFU lg2) is far cheaper than the software log1pf. z error ~1e-6 rel,
    // scaled by 0.001 -> negligible.
    float w = -__logf(fmaf(-x, x, 1.0f));
    float p;
    if (w < 5.0f) {
        w -= 2.5f;
        p =              2.81022636e-08f;
        p = fmaf(p, w,   3.43273939e-07f);
        p = fmaf(p, w,  -3.5233877e-06f);
        p = fmaf(p, w,  -4.39150654e-06f);
        p = fmaf(p, w,   0.00021858087f);
        p = fmaf(p, w,  -0.00125372503f);
        p = fmaf(p, w,  -0.00417768164f);
        p = fmaf(p, w,   0.246640727f);
        p = fmaf(p, w,   1.50140941f);
    } else {
        w = sqrtf(w) - 3.0f;
        p =             -0.000200214257f;
        p = fmaf(p, w,   0.000100950558f);
        p = fmaf(p, w,   0.00134934322f);
        p = fmaf(p, w,  -0.00367342844f);
        p = fmaf(p, w,   0.00573950773f);
        p = fmaf(p, w,  -0.0076224613f);
        p = fmaf(p, w,   0.00943887047f);
        p = fmaf(p, w,   1.00167406f);
        p = fmaf(p, w,   2.83297682f);
    }
    return 1.41421356237f * (p * x);
}

// ---------------- split helper ----------------
__device__ __forceinline__ void split_bf16(float v, __nv_bfloat16& hi, __nv_bfloat16& lo) {
    hi = __float2bfloat16(v);
    lo = __float2bfloat16(v - __bfloat162float(hi));
}

// ---------------- scan (smem season ring + x prefetch) + weight split ----------------
__global__ void scan_wsplit_kernel(const float* __restrict__ x,
                                   const float* __restrict__ lvl_coef,
                                   const float* __restrict__ seas_coef,
                                   const float* __restrict__ seas_params,
                                   const float* __restrict__ W1,
                                   const float* __restrict__ W2) {
    __shared__ float ring[512];
    if (blockIdx.x > 0) {
        int i = (blockIdx.x - 1) * 256 + threadIdx.x;
        if (i < WIN * WIN) split_bf16(W1[i], g_w1h[i], g_w1l[i]);
        if (i < WIN * OUTSZ) split_bf16(W2[i], g_w2h[i], g_w2l[i]);
        return;
    }
    if (threadIdx.x >= 32) return;
    const int lane = threadIdx.x;
    const unsigned FULL = 0xFFFFFFFFu;
    for (int i = lane; i < SEAS; i += 32) {
        float w = expf(seas_params[i]);
        ring[i] = w;
        g_wall[i] = w;
    }
    __syncwarp();
    if (lane == 0) { ring[SEAS] = ring[0]; g_wall[SEAS] = ring[0]; }
    __syncwarp();

    const float a = 1.0f / (1.0f + expf(-lvl_coef[0]));
    const float g = 1.0f / (1.0f + expf(-seas_coef[0]));
    const float b = 1.0f - a;
    const float omg = 1.0f - g;
    const float b5 = b * b * b * b * b;
    const float bl = __powf(b5, (float)lane);

    float level = x[0] / ring[0];
    if (lane == 0) g_levels[0] = level;

    float xn[LPL];
    {
        const int base = 1 + lane * LPL;
#pragma unroll
        for (int j = 0; j < LPL; j++)
            xn[j] = (base + j < T_LEN) ? __ldg(&x[base + j]) : 1.0f;
    }

    for (int t0 = 1; t0 < T_LEN; t0 += CHUNK) {
        const int base = t0 + lane * LPL;
        float xi[LPL];
#pragma unroll
        for (int j = 0; j < LPL; j++) xi[j] = xn[j];
        {
            const int nbase = t0 + CHUNK + lane * LPL;
#pragma unroll
            for (int j = 0; j < LPL; j++)
                xn[j] = (nbase + j < T_LEN) ? __ldg(&x[nbase + j]) : 1.0f;
        }
        float se[LPL], c[LPL];
#pragma unroll
        for (int j = 0; j < LPL; j++) {
            int t = base + j;
            if (t < T_LEN) {
                se[j] = ring[t & 511];
                c[j]  = __fdividef(a * xi[j], se[j]);
            } else { se[j] = 1.0f; c[j] = 0.0f; }
        }
        float s = 0.0f;
#pragma unroll
        for (int j = 0; j < LPL; j++) s = fmaf(b, s, c[j]);
        float S = s;
        float m = b5;
#pragma unroll
        for (int off = 1; off < 32; off <<= 1) {
            float up = __shfl_up_sync(FULL, S, off);
            if (lane >= off) S = fmaf(m, up, S);
            m = m * m;
        }
        float Sprev = __shfl_up_sync(FULL, S, 1);
        if (lane == 0) Sprev = 0.0f;
        float lvl = fmaf(bl, level, Sprev);
#pragma unroll
        for (int j = 0; j < LPL; j++) {
            int t = base + j;
            if (t < T_LEN) {
                lvl = fmaf(b, lvl, c[j]);
                g_levels[t] = lvl;
                float ns = fmaf(omg, se[j], __fdividef(g * xi[j], lvl));
                ring[(t + SEAS) & 511] = ns;
                if (t + SEAS < T_LEN) g_wall[t + SEAS] = ns;
            }
        }
        level = __shfl_sync(FULL, lvl, 31);
        __syncwarp();
    }
}

// ---------------- parallel log precompute ----------------
__global__ void prep_kernel(const float* __restrict__ x) {
    int i = blockIdx.x * blockDim.x + threadIdx.x;
    if (i < T_LEN) {
        g_llev[i] = logf(g_levels[i]);
        g_c[i]    = logf(x[i]) - logf(g_wall[i]);
    }
}

// ---------------- level variation loss ----------------
__global__ void loss_kernel(float* __restrict__ d_out) {
    __shared__ double sh[256];
    double acc = 0.0;
    for (int i = threadIdx.x; i < T_LEN - 2; i += 256) {
        float d2 = (g_llev[i + 2] - g_llev[i + 1]) - (g_llev[i + 1] - g_llev[i]);
        acc += (double)d2 * (double)d2;
    }
    sh[threadIdx.x] = acc;
    __syncthreads();
    for (int s = 128; s > 0; s >>= 1) {
        if (threadIdx.x < s) sh[threadIdx.x] += sh[threadIdx.x + s];
        __syncthreads();
    }
    if (threadIdx.x == 0)
        d_out[2 * (size_t)N_ROWS * OUTSZ] = (float)(sh[0] / (double)(T_LEN - 2) * (double)LVP_F);
}

// ---------------- inputs matrix -> bf16 hi/lo, incl. zero tail to M_PAD ----------------
__global__ void gen_inputs_kernel() {
    constexpr TF2 K1 = tf2x32_const(0u, 1u, 0u, 0u);
    const unsigned M = (unsigned)N_ROWS * WIN;
    const unsigned MP = (unsigned)M_PAD * WIN;
    unsigned t = blockIdx.x * blockDim.x + threadIdx.x;
    unsigned i0 = 4u * t;
    if (i0 >= MP) return;
    if (i0 >= M) {
        *reinterpret_cast<uint2*>(&g_a_hi[i0]) = make_uint2(0, 0);
        *reinterpret_cast<uint2*>(&g_a_lo[i0]) = make_uint2(0, 0);
        return;
    }
    __nv_bfloat16 hi[4], lo[4];
#pragma unroll
    for (int j = 0; j < 4; j++) {
        unsigned i = i0 + j;
        unsigned n = i / WIN, w = i - n * WIN;
        float z = bits_to_normal(tf_bits32(K1.y0, K1.y1, i));
        float v = g_c[n + w] - g_llev[n + WIN] + STD_NOISE * z;
        split_bf16(v, hi[j], lo[j]);
    }
    *reinterpret_cast<__nv_bfloat162*>(&g_a_hi[i0])     = __nv_bfloat162{hi[0], hi[1]};
    *reinterpret_cast<__nv_bfloat162*>(&g_a_hi[i0 + 2]) = __nv_bfloat162{hi[2], hi[3]};
    *reinterpret_cast<__nv_bfloat162*>(&g_a_lo[i0])     = __nv_bfloat162{lo[0], lo[1]};
    *reinterpret_cast<__nv_bfloat162*>(&g_a_lo[i0 + 2]) = __nv_bfloat162{lo[2], lo[3]};
}

// ---------------- labels directly into d_out ----------------
__global__ void gen_labels_kernel(float* __restrict__ d_out) {
    constexpr TF2 K2 = tf2x32_const(0u, 1u, 0u, 1u);
    const unsigned M = (unsigned)N_ROWS * OUTSZ;
    unsigned t = blockIdx.x * blockDim.x + threadIdx.x;
    unsigned i0 = 4u * t;
    if (i0 >= M) return;
    float* labels = d_out + (size_t)N_ROWS * OUTSZ;
    float v[4];
#pragma unroll
    for (int j = 0; j < 4; j++) {
        unsigned i = i0 + j;
        unsigned n = i / OUTSZ, o = i - n * OUTSZ;
        float z = bits_to_normal(tf_bits32(K2.y0, K2.y1, i));
        v[j] = g_c[n + WIN + o] - g_llev[n + WIN] + STD_NOISE * z;
    }
    *reinterpret_cast<float4*>(&labels[i0]) = make_float4(v[0], v[1], v[2], v[3]);
}

// ---------------- mma / cp.async helpers ----------------
__device__ __forceinline__ unsigned sm_u32(const void* p) {
    return (unsigned)__cvta_generic_to_shared(p);
}
__device__ __forceinline__ void ldsm_x4(unsigned* d, unsigned addr) {
    asm volatile("ldmatrix.sync.aligned.m8n8.x4.shared.b16 {%0,%1,%2,%3}, [%4];"
                 : "=r"(d[0]), "=r"(d[1]), "=r"(d[2]), "=r"(d[3]) : "r"(addr));
}
__device__ __forceinline__ void ldsm_x4t(unsigned* d, unsigned addr) {
    asm volatile("ldmatrix.sync.aligned.m8n8.x4.trans.shared.b16 {%0,%1,%2,%3}, [%4];"
                 : "=r"(d[0]), "=r"(d[1]), "=r"(d[2]), "=r"(d[3]) : "r"(addr));
}
__device__ __forceinline__ void mma16816(float* c, const unsigned* a, unsigned b0, unsigned b1) {
    asm volatile("mma.sync.aligned.m16n8k16.row.col.f32.bf16.bf16.f32 "
                 "{%0,%1,%2,%3}, {%4,%5,%6,%7}, {%8,%9}, {%0,%1,%2,%3};"
                 : "+f"(c[0]), "+f"(c[1]), "+f"(c[2]), "+f"(c[3])
                 : "r"(a[0]), "r"(a[1]), "r"(a[2]), "r"(a[3]), "r"(b0), "r"(b1));
}
__device__ __forceinline__ void cp16(void* s, const void* g) {
    asm volatile("cp.async.cg.shared.global [%0], [%1], 16;"
                 :: "r"(sm_u32(s)), "l"(g));
}
__device__ __forceinline__ void cp16_pred(void* s, const void* g, bool ok) {
    int sz = ok ? 16 : 0;
    asm volatile("cp.async.cg.shared.global [%0], [%1], 16, %2;"
                 :: "r"(sm_u32(s)), "l"(g), "r"(sz));
}
__device__ __forceinline__ void cp_commit() {
    asm volatile("cp.async.commit_group;");
}
template<int N>
__device__ __forceinline__ void cp_wait() {
    asm volatile("cp.async.wait_group %0;" :: "n"(N));
}

// ---------------- GEMM1: hidden = tanh(A@W1 + b1), 3-term bf16, 2-stage cp.async ----
#define G1_AST 72
#define G1_BST 136
__global__ void __launch_bounds__(256, 1)
gemm1_kernel(const float* __restrict__ bias) {
    extern __shared__ char smem[];
    const int tid = threadIdx.x;
    const int wid = tid >> 5, lane = tid & 31;
    const int wm = wid >> 2, wn = wid & 3;
    const int row0 = blockIdx.x * 128;
    const int col0 = blockIdx.y * 128;
    const int lrow = lane & 15, lcol = (lane >> 4) << 3;

    auto sAh = [&](int s) { return (__nv_bfloat16*)(smem + s * G1_STAGE); };
    auto sAl = [&](int s) { return (__nv_bfloat16*)(smem + s * G1_STAGE + 18432); };
    auto sBh = [&](int s) { return (__nv_bfloat16*)(smem + s * G1_STAGE + 36864); };
    auto sBl = [&](int s) { return (__nv_bfloat16*)(smem + s * G1_STAGE + 49920); };

    auto issue = [&](int k0_idx, int s) {
        const int k0 = k0_idx * 48;
        __nv_bfloat16 *ah = sAh(s), *al = sAl(s), *bh = sBh(s), *bl = sBl(s);
        for (int idx = tid; idx < 128 * 6; idx += 256) {
            int r = idx / 6, cb = (idx % 6) * 8;
            size_t go = (size_t)(row0 + r) * WIN + k0 + cb;
            cp16(&ah[r * G1_AST + cb], &g_a_hi[go]);
            cp16(&al[r * G1_AST + cb], &g_a_lo[go]);
        }
        for (int idx = tid; idx < 48 * 16; idx += 256) {
            int r = idx / 16, cb = (idx % 16) * 8;
            int gn = col0 + cb;
            bool ok = gn < WIN;
            size_t go = ok ? (size_t)(k0 + r) * WIN + gn : 0;
            cp16_pred(&bh[r * G1_BST + cb], &g_w1h[go], ok);
            cp16_pred(&bl[r * G1_BST + cb], &g_w1l[go], ok);
        }
    };

    float acc[4][4][4];
#pragma unroll
    for (int i = 0; i < 4; i++)
#pragma unroll
        for (int j = 0; j < 4; j++)
#pragma unroll
            for (int k = 0; k < 4; k++) acc[i][j][k] = 0.0f;

    issue(0, 0);
    cp_commit();

    for (int it = 0; it < 7; it++) {
        const int s = it & 1;
        if (it < 6) {
            issue(it + 1, s ^ 1);
            cp_commit();
            cp_wait<1>();
        } else {
            cp_wait<0>();
        }
        __syncthreads();

        __nv_bfloat16 *ah_s = sAh(s), *al_s = sAl(s), *bh_s = sBh(s), *bl_s = sBl(s);
#pragma unroll
        for (int ks = 0; ks < 3; ks++) {
            unsigned bh[2][4], bl[2][4];
#pragma unroll
            for (int nf2 = 0; nf2 < 2; nf2++) {
                unsigned addr = sm_u32(&bh_s[(ks * 16 + lrow) * G1_BST + wn * 32 + nf2 * 16 + lcol]);
                ldsm_x4t(bh[nf2], addr);
                addr = sm_u32(&bl_s[(ks * 16 + lrow) * G1_BST + wn * 32 + nf2 * 16 + lcol]);
                ldsm_x4t(bl[nf2], addr);
            }
#pragma unroll
            for (int mf = 0; mf < 4; mf++) {
                unsigned ah[4], al[4];
                unsigned addr = sm_u32(&ah_s[(wm * 64 + mf * 16 + lrow) * G1_AST + ks * 16 + lcol]);
                ldsm_x4(ah, addr);
                addr = sm_u32(&al_s[(wm * 64 + mf * 16 + lrow) * G1_AST + ks * 16 + lcol]);
                ldsm_x4(al, addr);
#pragma unroll
                for (int nf2 = 0; nf2 < 2; nf2++) {
#pragma unroll
                    for (int h = 0; h < 2; h++) {
                        int n8 = nf2 * 2 + h;
                        mma16816(acc[mf][n8], ah, bh[nf2][2 * h], bh[nf2][2 * h + 1]);
                        mma16816(acc[mf][n8], al, bh[nf2][2 * h], bh[nf2][2 * h + 1]);
                        mma16816(acc[mf][n8], ah, bl[nf2][2 * h], bl[nf2][2 * h + 1]);
                    }
                }
            }
        }
        __syncthreads();
    }

    const int group = lane >> 2, tig = lane & 3;
#pragma unroll
    for (int mf = 0; mf < 4; mf++) {
#pragma unroll
        for (int n8 = 0; n8 < 4; n8++) {
            int gc = col0 + wn * 32 + n8 * 8 + 2 * tig;
            if (gc >= WIN) continue;
            float b0 = bias[gc], b1 = bias[gc + 1];
            int r0 = row0 + wm * 64 + mf * 16 + group;
#pragma unroll
            for (int half = 0; half < 2; half++) {
                int gr = r0 + half * 8;
                float t0 = tanhf(acc[mf][n8][2 * half] + b0);
                float t1 = tanhf(acc[mf][n8][2 * half + 1] + b1);
                __nv_bfloat16 h0, l0, h1, l1;
                split_bf16(t0, h0, l0);
                split_bf16(t1, h1, l1);
                size_t go = (size_t)gr * WIN + gc;
                *reinterpret_cast<__nv_bfloat162*>(&g_h_hi[go]) = __nv_bfloat162{h0, h1};
                *reinterpret_cast<__nv_bfloat162*>(&g_h_lo[go]) = __nv_bfloat162{l0, l1};
            }
        }
    }
}

// ---------------- GEMM2: out = hidden@W2 + b2, 3-term bf16, 2-stage cp.async ------
// 2 CTAs/SM (regs capped at 128) so sync/latency gaps are covered cross-CTA.
#define G2_BST 72
__global__ void __launch_bounds__(256, 2)
gemm2_kernel(const float* __restrict__ bias, float* __restrict__ out) {
    extern __shared__ char smem[];
    const int tid = threadIdx.x;
    const int wid = tid >> 5, lane = tid & 31;
    const int row0 = blockIdx.x * 128;
    const int lrow = lane & 15, lcol = (lane >> 4) << 3;

    auto sAh = [&](int s) { return (__nv_bfloat16*)(smem + s * G2_STAGE); };
    auto sAl = [&](int s) { return (__nv_bfloat16*)(smem + s * G2_STAGE + 18432); };
    auto sBh = [&](int s) { return (__nv_bfloat16*)(smem + s * G2_STAGE + 36864); };
    auto sBl = [&](int s) { return (__nv_bfloat16*)(smem + s * G2_STAGE + 43776); };

    auto issue = [&](int k0_idx, int s) {
        const int k0 = k0_idx * 48;
        __nv_bfloat16 *ah = sAh(s), *al = sAl(s), *bh = sBh(s), *bl = sBl(s);
        for (int idx = tid; idx < 128 * 6; idx += 256) {
            int r = idx / 6, cb = (idx % 6) * 8;
            size_t go = (size_t)(row0 + r) * WIN + k0 + cb;
            cp16(&ah[r * G1_AST + cb], &g_h_hi[go]);
            cp16(&al[r * G1_AST + cb], &g_h_lo[go]);
        }
        for (int idx = tid; idx < 48 * 6; idx += 256) {
            int r = idx / 6, cb = (idx % 6) * 8;
            size_t go = (size_t)(k0 + r) * OUTSZ + cb;
            cp16(&bh[r * G2_BST + cb], &g_w2h[go]);
            cp16(&bl[r * G2_BST + cb], &g_w2l[go]);
        }
    };

    float acc[6][4];
#pragma unroll
    for (int i = 0; i < 6; i++)
#pragma unroll
        for (int k = 0; k < 4; k++) acc[i][k] = 0.0f;

    issue(0, 0);
    cp_commit();

    for (int it = 0; it < 7; it++) {
        const int s = it & 1;
        if (it < 6) {
            issue(it + 1, s ^ 1);
            cp_commit();
            cp_wait<1>();
        } else {
            cp_wait<0>();
        }
        __syncthreads();

        __nv_bfloat16 *ah_s = sAh(s), *al_s = sAl(s), *bh_s = sBh(s), *bl_s = sBl(s);
#pragma unroll
        for (int ks = 0; ks < 3; ks++) {
            unsigned ah[4], al[4];
            unsigned addr = sm_u32(&ah_s[(wid * 16 + lrow) * G1_AST + ks * 16 + lcol]);
            ldsm_x4(ah, addr);
            addr = sm_u32(&al_s[(wid * 16 + lrow) * G1_AST + ks * 16 + lcol]);
            ldsm_x4(al, addr);
#pragma unroll
            for (int nf2 = 0; nf2 < 3; nf2++) {
                unsigned bh[4], bl[4];
                addr = sm_u32(&bh_s[(ks * 16 + lrow) * G2_BST + nf2 * 16 + lcol]);
                ldsm_x4t(bh, addr);
                addr = sm_u32(&bl_s[(ks * 16 + lrow) * G2_BST + nf2 * 16 + lcol]);
                ldsm_x4t(bl, addr);
#pragma unroll
                for (int h = 0; h < 2; h++) {
                    int n8 = nf2 * 2 + h;
                    mma16816(acc[n8], ah, bh[2 * h], bh[2 * h + 1]);
                    mma16816(acc[n8], al, bh[2 * h], bh[2 * h + 1]);
                    mma16816(acc[n8], ah, bl[2 * h], bl[2 * h + 1]);
                }
            }
        }
        __syncthreads();
    }

    const int group = lane >> 2, tig = lane & 3;
#pragma unroll
    for (int n8 = 0; n8 < 6; n8++) {
        int gc = n8 * 8 + 2 * tig;
        float b0 = bias[gc], b1 = bias[gc + 1];
        int r0 = row0 + wid * 16 + group;
#pragma unroll
        for (int half = 0; half < 2; half++) {
            int gr = r0 + half * 8;
            if (gr < N_ROWS) {
                float2 v = make_float2(acc[n8][2 * half] + b0, acc[n8][2 * half + 1] + b1);
                *reinterpret_cast<float2*>(&out[(size_t)gr * OUTSZ + gc]) = v;
            }
        }
    }
}

// ---------------- launch ----------------
extern "C" void kernel_launch(void* const* d_in, const int* in_sizes, int n_in,
                              void* d_out, int out_size) {
    const float* x           = (const float*)d_in[0];
    const float* lvl_coef    = (const float*)d_in[1];
    const float* seas_coef   = (const float*)d_in[2];
    const float* seas_params = (const float*)d_in[3];
    const float* W_tanh      = (const float*)d_in[4];
    const float* b_tanh      = (const float*)d_in[5];
    const float* W_out       = (const float*)d_in[6];
    const float* b_out       = (const float*)d_in[7];
    float* out = (float*)d_out;

    cudaFuncSetAttribute(gemm1_kernel, cudaFuncAttributeMaxDynamicSharedMemorySize, G1_SMEM);
    cudaFuncSetAttribute(gemm2_kernel, cudaFuncAttributeMaxDynamicSharedMemorySize, G2_SMEM);

    // gemm1 stays at launch index 3 (profiled by the harness ncu capture)
    scan_wsplit_kernel<<<1 + (WIN * WIN + 255) / 256, 256>>>(
        x, lvl_coef, seas_coef, seas_params, W_tanh, W_out);
    prep_kernel<<<(T_LEN + 255) / 256, 256>>>(x);
    {
        unsigned P = ((unsigned)M_PAD * WIN) / 4u;
        gen_inputs_kernel<<<(P + 255) / 256, 256>>>();
    }
    {
        dim3 grid(M_PAD / 128, 3);
        gemm1_kernel<<<grid, 256, G1_SMEM>>>(b_tanh);
    }
    {
        unsigned P = ((unsigned)N_ROWS * OUTSZ) / 4u;
        gen_labels_kernel<<<(P + 255) / 256, 256>>>(out);
    }
    loss_kernel<<<1, 256>>>(out);
    {
        dim3 grid(M_PAD / 128);
        gemm2_kernel<<<grid, 256, G2_SMEM>>>(b_out, out);
    }
    (void)in_sizes; (void)n_in; (void)out_size;
}